// round 12
// baseline (speedup 1.0000x reference)
#include <cuda_runtime.h>
#include <cuda_fp16.h>
#include <cstdint>
#include <math.h>

// Problem constants
#define LL 1024
#define BB 2
#define FF 1024
#define HH 2048
#define NN 16
#define RR 64
#define KK 4
#define MROWS (LL*BB)        // 2048
#define PROJC (RR + 2*NN)    // 96

typedef __half h16;

// ---------------- scratch (device globals: allocation-free) ----------------
__device__ h16 g_xh [(size_t)MROWS * FF];
__device__ h16 g_Win[(size_t)(2*HH) * FF];      // [4096][1024] K-major
__device__ h16 g_xs [(size_t)MROWS * HH];
__device__ h16 g_Wc [(size_t)HH * (KK*1024)];   // [2048][4096]
__device__ h16 g_uh [(size_t)MROWS * HH];
__device__ h16 g_resh[(size_t)MROWS * HH];
__device__ h16 g_Ws [(size_t)128 * HH];         // [128 pad][2048]
__device__ h16 g_dth[(size_t)MROWS * RR];
__device__ h16 g_Wd [(size_t)HH * RR];          // [2048][64]
__device__ h16 g_zh [(size_t)MROWS * HH];
__device__ h16 g_Wo [(size_t)FF * HH];          // [1024][2048]
// fp32 intermediates for the scan
__device__ float g_proj [(size_t)MROWS * PROJC];
__device__ float g_delta[(size_t)MROWS * HH];

// ---------------- tiling ----------------------------------------------------
#define BM 128
#define BN 128
#define BK 32
#define NTHR 512                          // 16 warps: 4 (m) x 4 (n)
#define ROW_B   80                        // 32 halves (64B) + 16B pad
#define ARR_B   (128 * ROW_B)             // 10240 B per operand tile
#define STAGE_B (2 * ARR_B)               // A + B = 20480 B
#define NSTAGE  3
#define SMEM_TOTAL (NSTAGE * STAGE_B)     // 61440 B

__device__ __forceinline__ float sigmoid_f(float x) {
    return 1.f / (1.f + __expf(-x));
}
__device__ __forceinline__ void mma_f16(float* d, const unsigned* a, const unsigned* b) {
    asm volatile(
        "mma.sync.aligned.m16n8k16.row.col.f32.f16.f16.f32 "
        "{%0,%1,%2,%3}, {%4,%5,%6,%7}, {%8,%9}, {%0,%1,%2,%3};\n"
        : "+f"(d[0]), "+f"(d[1]), "+f"(d[2]), "+f"(d[3])
        : "r"(a[0]), "r"(a[1]), "r"(a[2]), "r"(a[3]), "r"(b[0]), "r"(b[1]));
}
__device__ __forceinline__ void ldm_x4(unsigned* r, unsigned saddr) {
    asm volatile("ldmatrix.sync.aligned.m8n8.x4.shared.b16 {%0,%1,%2,%3}, [%4];"
        : "=r"(r[0]), "=r"(r[1]), "=r"(r[2]), "=r"(r[3]) : "r"(saddr));
}
__device__ __forceinline__ void cp16(void* smem_dst, const void* gsrc, bool valid) {
    unsigned s = (unsigned)__cvta_generic_to_shared(smem_dst);
    int sz = valid ? 16 : 0;
    asm volatile("cp.async.cg.shared.global [%0], [%1], 16, %2;\n"
                 :: "r"(s), "l"(gsrc), "r"(sz));
}
#define CP_COMMIT() asm volatile("cp.async.commit_group;\n")
#define CP_WAIT(n)  asm volatile("cp.async.wait_group %0;\n" :: "n"(n))

// ---------------- pre-passes -------------------------------------------------
// in [Kd][Nd] fp32 -> out [Npad][Kd] fp16 (rows >= Nd zero)
__device__ __forceinline__ void tr_body(const float* __restrict__ in,
                                        h16* __restrict__ o,
                                        int Kd, int Nd, int Npad,
                                        int k0, int n0)
{
    __shared__ float tile[32][33];
    for (int i = threadIdx.y; i < 32; i += 8) {
        int k = k0 + i, n = n0 + threadIdx.x;
        tile[i][threadIdx.x] = (k < Kd && n < Nd) ? in[(size_t)k * Nd + n] : 0.f;
    }
    __syncthreads();
    for (int i = threadIdx.y; i < 32; i += 8) {
        int n = n0 + i, k = k0 + threadIdx.x;
        if (n < Npad && k < Kd)
            o[(size_t)n * Kd + k] = __float2half_rn(tile[threadIdx.x][i]);
    }
}

// launch 1: blocks [0,8192): tohalf(x); blocks [8192, 16384): trhalf(W_conv)
__global__ void cvt1_k(const float* __restrict__ x, h16* __restrict__ xh,
                       const float* __restrict__ Wc_in, h16* __restrict__ Wc_o)
{
    int bid = blockIdx.x;
    int t = threadIdx.y * 32 + threadIdx.x;
    if (bid < 8192) {
        int i = bid * 256 + t;                   // MROWS*FF = 2M elements
        if (i < MROWS * FF) xh[i] = __float2half_rn(x[i]);
    } else {
        int b2 = bid - 8192;                     // 128 x 64 blocks
        int kb = b2 & 127, nb = b2 >> 7;
        tr_body(Wc_in, Wc_o, KK * 1024, HH, HH, kb * 32, nb * 32);
    }
}

__global__ void trhalf_k(const float* __restrict__ in, h16* __restrict__ o,
                         int Kd, int Nd, int Npad)
{
    tr_body(in, o, Kd, Nd, Npad, blockIdx.x * 32, blockIdx.y * 32);
}

// fused transpose of W_ssm, W_dt, W_out (blocks: 256 + 128 + 2048)
__global__ void tr3_k(const float* __restrict__ Ws_in, h16* __restrict__ Ws_o,
                      const float* __restrict__ Wd_in, h16* __restrict__ Wd_o,
                      const float* __restrict__ Wo_in, h16* __restrict__ Wo_o)
{
    int bid = blockIdx.x;
    if (bid < 256) {            // W_ssm: Kd=HH, Nd=96, Npad=128 -> 64 x 4
        int kb = bid & 63, nb = bid >> 6;
        tr_body(Ws_in, Ws_o, HH, PROJC, 128, kb * 32, nb * 32);
    } else if (bid < 384) {     // W_dt: Kd=64, Nd=HH -> 2 x 64
        int b2 = bid - 256;
        int kb = b2 & 1, nb = b2 >> 1;
        tr_body(Wd_in, Wd_o, RR, HH, HH, kb * 32, nb * 32);
    } else {                    // W_out: Kd=HH, Nd=FF -> 64 x 32
        int b2 = bid - 384;
        int kb = b2 & 63, nb = b2 >> 6;
        tr_body(Wo_in, Wo_o, HH, FF, FF, kb * 32, nb * 32);
    }
}

// ===== fp16 tensor GEMM: 128x128xK tile, 512 thr (4x4 warps, 32x32/warp) ===
// C = A[M,K] @ B[N,K]^T, fp32 accum.
// EPI 0: GEMM1  (c<HH -> fp16 Ch=xs; else fp16 Ch2=res at col c-HH)
// EPI 1: conv   (silu(v+bias) -> fp16 Ch=u)
// EPI 2: proj   (c<96 -> Cf[96]; 32<=c<96 -> fp16 Ch=dt at col c-32)
// EPI 3: delta  (softplus(v+bias) -> Cf fp32)
// EPI 4: out    (Cf plain fp32)
template<int EPI, int CONV>
__global__ __launch_bounds__(NTHR, 2)
void tc_gemm(const h16* __restrict__ A, int lda,
             const h16* __restrict__ B, int ldb,
             float* __restrict__ Cf, h16* __restrict__ Ch, h16* __restrict__ Ch2,
             int Nn, int Kk, const float* __restrict__ bias)
{
    extern __shared__ __align__(16) char smem[];
    const unsigned smb = (unsigned)__cvta_generic_to_shared(smem);

    const int tid  = threadIdx.x;
    const int col0 = blockIdx.x * BN;
    const int row0 = blockIdx.y * BM;
    const int grp  = CONV ? (col0 >> 10) : 0;
    const int warp = tid >> 5;
    const int lane = tid & 31;
    const int gid  = lane >> 2;        // 0..7
    const int tig  = lane & 3;         // 0..3
    const int wm0  = (warp & 3) * 32;  // warp m origin
    const int wn0  = (warp >> 2) * 32; // warp n origin
    const int sel  = lane >> 3;        // 0..3 (ldmatrix quadrant)
    const int lr   = lane & 7;         // 0..7 (ldmatrix row)

    auto ld_tile = [&](int kt, int stage) {
        char* base = smem + stage * STAGE_B;
        {   // A: 128 rows x 32 halves = 512 x 16B, one per thread
            int m = tid >> 2, j = (tid & 3) * 8;
            char* dst = base + m * ROW_B + j * 2;
            const h16* src;
            bool valid = true;
            if (CONV) {
                int tap = kt >> 10, ci0 = kt & 1023, shift = 2 * (3 - tap);
                int rs = row0 + m - shift;
                valid = rs >= 0;
                src = A + (size_t)(valid ? rs : 0) * lda + grp * 1024 + ci0 + j;
            } else {
                src = A + (size_t)(row0 + m) * lda + kt + j;
            }
            cp16(dst, src, valid);
        }
        {   // B: 128 rows x 32 halves, one per thread
            int n = tid >> 2, j = (tid & 3) * 8;
            cp16(base + ARR_B + n * ROW_B + j * 2,
                 B + (size_t)(col0 + n) * ldb + kt + j, true);
        }
        CP_COMMIT();
    };

    float acc[2][4][4];
#pragma unroll
    for (int mt = 0; mt < 2; mt++)
#pragma unroll
        for (int nt = 0; nt < 4; nt++)
#pragma unroll
            for (int q = 0; q < 4; q++) acc[mt][nt][q] = 0.f;

    const int T = Kk / BK;
    ld_tile(0, 0);
    if (T > 1) ld_tile(BK, 1);

    for (int t = 0; t < T; t++) {
        const int stage = t % NSTAGE;
        if (t + 1 < T) CP_WAIT(1); else CP_WAIT(0);
        __syncthreads();
        if (t + 2 < T) ld_tile((t + 2) * BK, (t + 2) % NSTAGE);

        const unsigned Abase = smb + stage * STAGE_B;
        const unsigned Bbase = Abase + ARR_B;

#pragma unroll
        for (int c = 0; c < 2; c++) {             // two k16 chunks
            unsigned a[2][4], b[4][2];
#pragma unroll
            for (int mt = 0; mt < 2; mt++) {
                int row  = wm0 + mt * 16 + ((sel & 1) << 3) + lr;
                int wcol = c * 8 + ((sel >> 1) << 2);
                ldm_x4(a[mt], Abase + row * ROW_B + wcol * 4);
            }
#pragma unroll
            for (int pr = 0; pr < 2; pr++) {      // pairs of n8 tiles
                unsigned r4[4];
                int row  = wn0 + pr * 16 + ((sel >> 1) << 3) + lr;
                int wcol = c * 8 + ((sel & 1) << 2);
                ldm_x4(r4, Bbase + row * ROW_B + wcol * 4);
                b[pr * 2][0]     = r4[0]; b[pr * 2][1]     = r4[1];
                b[pr * 2 + 1][0] = r4[2]; b[pr * 2 + 1][1] = r4[3];
            }
#pragma unroll
            for (int mt = 0; mt < 2; mt++)
#pragma unroll
                for (int nt = 0; nt < 4; nt++)
                    mma_f16(acc[mt][nt], a[mt], b[nt]);
        }
        __syncthreads();
    }

    auto epi_store = [&](int r, int c, float v) {
        if (EPI == 0) {
            if (c < HH) Ch[(size_t)r * HH + c] = __float2half_rn(v);
            else        Ch2[(size_t)r * HH + (c - HH)] = __float2half_rn(v);
        } else if (EPI == 1) {
            v += bias[c]; v = v * sigmoid_f(v);
            Ch[(size_t)r * HH + c] = __float2half_rn(v);
        } else if (EPI == 2) {
            if (c < PROJC) {
                Cf[(size_t)r * PROJC + c] = v;
                if (c >= 2 * NN)
                    Ch[(size_t)r * RR + (c - 2 * NN)] = __float2half_rn(v);
            }
        } else if (EPI == 3) {
            v += bias[c];
            v = (v > 20.f) ? v : log1pf(expf(v));
            Cf[(size_t)r * HH + c] = v;
        } else {
            Cf[(size_t)r * FF + c] = v;
        }
    };

#pragma unroll
    for (int mt = 0; mt < 2; mt++) {
        int r = row0 + wm0 + mt * 16 + gid;
#pragma unroll
        for (int nt = 0; nt < 4; nt++) {
            int c = col0 + wn0 + nt * 8 + tig * 2;
            epi_store(r,     c,     acc[mt][nt][0]);
            epi_store(r,     c + 1, acc[mt][nt][1]);
            epi_store(r + 8, c,     acc[mt][nt][2]);
            epi_store(r + 8, c + 1, acc[mt][nt][3]);
        }
    }
}

// ---------------- selective scan + fused z = y * silu(res) ----------------
__global__ __launch_bounds__(256)
void scan_k(const float* __restrict__ delta, const h16* __restrict__ uh,
            const float* __restrict__ proj, const float* __restrict__ A_log,
            const float* __restrict__ D, const h16* __restrict__ resh,
            h16* __restrict__ zh)
{
    const int gtid = blockIdx.x * blockDim.x + threadIdx.x;
    const int warp = gtid >> 5;
    const int lane = threadIdx.x & 31;
    const int sub  = lane >> 4;
    const int n    = lane & 15;
    const int c    = warp * 2 + sub;
    const int hi   = c >> 1;
    const int b    = c & 1;

    const float A  = -expf(A_log[hi * NN + n]);
    const float Dh = D[hi];
    float s = 0.f;

    for (int t = 0; t < LL; t++) {
        const int r = t * BB + b;
        float dt = __ldg(&delta[(size_t)r * HH + hi]);
        dt = fminf(fmaxf(dt, 0.001f), 0.1f);
        const float uu = __half2float(__ldg(&uh[(size_t)r * HH + hi]));
        const float Bn = __ldg(&proj[(size_t)r * PROJC + n]);
        const float Cn = __ldg(&proj[(size_t)r * PROJC + NN + n]);

        s = __expf(dt * A) * s + (dt * uu) * Bn;

        float p = Cn * s;
        p += __shfl_xor_sync(0xffffffffu, p, 1);
        p += __shfl_xor_sync(0xffffffffu, p, 2);
        p += __shfl_xor_sync(0xffffffffu, p, 4);
        p += __shfl_xor_sync(0xffffffffu, p, 8);

        if (n == 0) {
            const float yv = p + uu * Dh;
            const float rv = __half2float(__ldg(&resh[(size_t)r * HH + hi]));
            zh[(size_t)r * HH + hi] = __float2half_rn(yv * (rv * sigmoid_f(rv)));
        }
    }
}

// ---------------- launch ---------------------------------------------------
extern "C" void kernel_launch(void* const* d_in, const int* in_sizes, int n_in,
                              void* d_out, int out_size)
{
    const float* x      = (const float*)d_in[0];
    const float* W_in   = (const float*)d_in[1];
    const float* W_conv = (const float*)d_in[2];
    const float* b_conv = (const float*)d_in[3];
    const float* A_log  = (const float*)d_in[4];
    const float* D      = (const float*)d_in[5];
    const float* W_ssm  = (const float*)d_in[6];
    const float* W_dt   = (const float*)d_in[7];
    const float* b_dt   = (const float*)d_in[8];
    const float* W_out  = (const float*)d_in[9];
    float* out = (float*)d_out;

    void* p;
#define SYM(v, s) cudaGetSymbolAddress(&p, s); auto* v = decltype(&s[0])(p)
    SYM(xh, g_xh);   SYM(Win, g_Win);
    SYM(xs, g_xs);   SYM(Wc, g_Wc);
    SYM(uh, g_uh);   SYM(resh, g_resh);
    SYM(Ws, g_Ws);
    SYM(dth, g_dth); SYM(Wd, g_Wd);
    SYM(zh, g_zh);   SYM(Wo, g_Wo);
    SYM(pb, g_proj); SYM(db, g_delta);
#undef SYM

    cudaFuncSetAttribute(tc_gemm<0,0>, cudaFuncAttributeMaxDynamicSharedMemorySize, SMEM_TOTAL);
    cudaFuncSetAttribute(tc_gemm<1,1>, cudaFuncAttributeMaxDynamicSharedMemorySize, SMEM_TOTAL);
    cudaFuncSetAttribute(tc_gemm<2,0>, cudaFuncAttributeMaxDynamicSharedMemorySize, SMEM_TOTAL);
    cudaFuncSetAttribute(tc_gemm<3,0>, cudaFuncAttributeMaxDynamicSharedMemorySize, SMEM_TOTAL);
    cudaFuncSetAttribute(tc_gemm<4,0>, cudaFuncAttributeMaxDynamicSharedMemorySize, SMEM_TOTAL);

    dim3 gblk(NTHR);
    dim3 blk(256);
    dim3 tblk(32, 8);

    // 1) x -> fp16 AND W_conv transpose (fused)
    cvt1_k<<<8192 + 8192, tblk>>>(x, xh, W_conv, Wc);

    // 2) W_in transpose
    trhalf_k<<<dim3(FF / 32, (2 * HH) / 32), tblk>>>(W_in, Win, FF, 2 * HH, 2 * HH);

    // 3) h = x @ W_in : xs -> fp16 g_xs, res -> fp16 g_resh
    tc_gemm<0, 0><<<dim3(2 * HH / BN, MROWS / BM), gblk, SMEM_TOTAL>>>(
        xh, FF, Win, FF, nullptr, xs, resh, 2 * HH, FF, nullptr);

    // 4) u = silu(conv(xs) + b_conv) -> fp16 g_uh   [ncu capture slot]
    tc_gemm<1, 1><<<dim3(HH / BN, MROWS / BM), gblk, SMEM_TOTAL>>>(
        xs, HH, Wc, KK * 1024, nullptr, uh, nullptr, HH, KK * 1024, b_conv);

    // 5) transpose W_ssm / W_dt / W_out
    tr3_k<<<256 + 128 + 2048, tblk>>>(W_ssm, Ws, W_dt, Wd, W_out, Wo);

    // 6) proj = u @ W_ssm -> fp32 g_proj; dt cols -> fp16 g_dth
    tc_gemm<2, 0><<<dim3(1, MROWS / BM), gblk, SMEM_TOTAL>>>(
        uh, HH, Ws, HH, pb, dth, nullptr, PROJC, HH, nullptr);

    // 7) delta = softplus(dt @ W_dt + b_dt) -> fp32 g_delta
    tc_gemm<3, 0><<<dim3(HH / BN, MROWS / BM), gblk, SMEM_TOTAL>>>(
        dth, RR, Wd, RR, db, nullptr, nullptr, HH, RR, b_dt);

    // 8) selective scan + z = y * silu(res) -> fp16 g_zh
    scan_k<<<BB * HH * NN / 256, blk>>>(db, uh, pb, A_log, D, resh, zh);

    // 9) out = z @ W_out -> fp32 out
    tc_gemm<4, 0><<<dim3(FF / BN, MROWS / BM), gblk, SMEM_TOTAL>>>(
        zh, HH, Wo, HH, out, nullptr, nullptr, FF, HH, nullptr);
}

// round 14
// speedup vs baseline: 2.1487x; 2.1487x over previous
#include <cuda_runtime.h>
#include <cuda_fp16.h>
#include <cstdint>
#include <math.h>

// Problem constants
#define LL 1024
#define BB 2
#define FF 1024
#define HH 2048
#define NN 16
#define RR 64
#define KK 4
#define MROWS (LL*BB)        // 2048
#define PROJC (RR + 2*NN)    // 96

typedef __half h16;

// ---------------- scratch (device globals: allocation-free) ----------------
__device__ h16 g_xh [(size_t)MROWS * FF];
__device__ h16 g_Win[(size_t)(2*HH) * FF];      // [4096][1024] K-major
__device__ h16 g_xs [(size_t)MROWS * HH];
__device__ h16 g_Wc [(size_t)HH * (KK*1024)];   // [2048][4096]
__device__ h16 g_uh [(size_t)MROWS * HH];       // u row-major (proj GEMM A)
__device__ h16 g_Ws [(size_t)128 * HH];         // [128 pad][2048]
__device__ h16 g_dth[(size_t)MROWS * RR];
__device__ h16 g_Wd [(size_t)HH * RR];          // [2048][64]
__device__ h16 g_zh [(size_t)MROWS * HH];
__device__ h16 g_Wo [(size_t)FF * HH];          // [1024][2048]
// time-major scan inputs: [channel][b][t]
__device__ float g_dtt [(size_t)HH * MROWS];    // delta  [hi][b][t]
__device__ h16   g_ut  [(size_t)HH * MROWS];    // u      [hi][b][t]
__device__ h16   g_rest[(size_t)HH * MROWS];    // res    [hi][b][t]
__device__ float g_Bt  [(size_t)NN * MROWS];    // B      [n][b][t]
__device__ float g_Ct  [(size_t)NN * MROWS];    // C      [n][b][t]

// transposed (time-major) index for scan tensors: r = t*2+b
#define TIX(r, c) ((size_t)(c) * MROWS + ((r) & 1) * LL + ((r) >> 1))

// ---------------- tiling ----------------------------------------------------
#define BM 128
#define BN 128
#define BK 32
#define ROW_B   80                        // 32 halves (64B) + 16B pad
#define ARR_B   (128 * ROW_B)             // 10240 B per operand tile
#define STAGE_B (2 * ARR_B)               // A + B = 20480 B
#define NSTAGE  3
#define SMEM_TOTAL (NSTAGE * STAGE_B)     // 61440 B

__device__ __forceinline__ float sigmoid_f(float x) {
    return 1.f / (1.f + __expf(-x));
}
__device__ __forceinline__ void mma_f16(float* d, const unsigned* a, const unsigned* b) {
    asm volatile(
        "mma.sync.aligned.m16n8k16.row.col.f32.f16.f16.f32 "
        "{%0,%1,%2,%3}, {%4,%5,%6,%7}, {%8,%9}, {%0,%1,%2,%3};\n"
        : "+f"(d[0]), "+f"(d[1]), "+f"(d[2]), "+f"(d[3])
        : "r"(a[0]), "r"(a[1]), "r"(a[2]), "r"(a[3]), "r"(b[0]), "r"(b[1]));
}
__device__ __forceinline__ void ldm_x4(unsigned* r, unsigned saddr) {
    asm volatile("ldmatrix.sync.aligned.m8n8.x4.shared.b16 {%0,%1,%2,%3}, [%4];"
        : "=r"(r[0]), "=r"(r[1]), "=r"(r[2]), "=r"(r[3]) : "r"(saddr));
}
__device__ __forceinline__ void cp16(void* smem_dst, const void* gsrc, bool valid) {
    unsigned s = (unsigned)__cvta_generic_to_shared(smem_dst);
    int sz = valid ? 16 : 0;
    asm volatile("cp.async.cg.shared.global [%0], [%1], 16, %2;\n"
                 :: "r"(s), "l"(gsrc), "r"(sz));
}
#define CP_COMMIT() asm volatile("cp.async.commit_group;\n")
#define CP_WAIT(n)  asm volatile("cp.async.wait_group %0;\n" :: "n"(n))

// ---------------- pre-passes -------------------------------------------------
__device__ __forceinline__ void tr_body(const float* __restrict__ in,
                                        h16* __restrict__ o,
                                        int Kd, int Nd, int Npad,
                                        int k0, int n0)
{
    __shared__ float tile[32][33];
    for (int i = threadIdx.y; i < 32; i += 8) {
        int k = k0 + i, n = n0 + threadIdx.x;
        tile[i][threadIdx.x] = (k < Kd && n < Nd) ? in[(size_t)k * Nd + n] : 0.f;
    }
    __syncthreads();
    for (int i = threadIdx.y; i < 32; i += 8) {
        int n = n0 + i, k = k0 + threadIdx.x;
        if (n < Npad && k < Kd)
            o[(size_t)n * Kd + k] = __float2half_rn(tile[threadIdx.x][i]);
    }
}

// launch 1: blocks [0,8192): tohalf(x); blocks [8192, 16384): trhalf(W_conv)
__global__ void cvt1_k(const float* __restrict__ x, h16* __restrict__ xh,
                       const float* __restrict__ Wc_in, h16* __restrict__ Wc_o)
{
    int bid = blockIdx.x;
    int t = threadIdx.y * 32 + threadIdx.x;
    if (bid < 8192) {
        int i = bid * 256 + t;
        if (i < MROWS * FF) xh[i] = __float2half_rn(x[i]);
    } else {
        int b2 = bid - 8192;
        int kb = b2 & 127, nb = b2 >> 7;
        tr_body(Wc_in, Wc_o, KK * 1024, HH, HH, kb * 32, nb * 32);
    }
}

__global__ void trhalf_k(const float* __restrict__ in, h16* __restrict__ o,
                         int Kd, int Nd, int Npad)
{
    tr_body(in, o, Kd, Nd, Npad, blockIdx.x * 32, blockIdx.y * 32);
}

__global__ void tr3_k(const float* __restrict__ Ws_in, h16* __restrict__ Ws_o,
                      const float* __restrict__ Wd_in, h16* __restrict__ Wd_o,
                      const float* __restrict__ Wo_in, h16* __restrict__ Wo_o)
{
    int bid = blockIdx.x;
    if (bid < 256) {            // W_ssm
        int kb = bid & 63, nb = bid >> 6;
        tr_body(Ws_in, Ws_o, HH, PROJC, 128, kb * 32, nb * 32);
    } else if (bid < 384) {     // W_dt
        int b2 = bid - 256;
        int kb = b2 & 1, nb = b2 >> 1;
        tr_body(Wd_in, Wd_o, RR, HH, HH, kb * 32, nb * 32);
    } else {                    // W_out
        int b2 = bid - 384;
        int kb = b2 & 63, nb = b2 >> 6;
        tr_body(Wo_in, Wo_o, HH, FF, FF, kb * 32, nb * 32);
    }
}

// ===== fp16 tensor GEMM: 128x128xK tile, 256 thr (8 warps, 32x64/warp) =====
// EPI 0: GEMM1 (c<HH -> fp16 Ch=xs; else h16 Ch2 = res TIME-MAJOR)
// EPI 1: conv  (silu(v+bias) -> fp16 Ch=u row-major AND Ch2=u time-major)
// EPI 2: proj  (c<16->Bt tm fp32 via Cf; c<32->Ct tm fp32 via Ch2-cast;
//               32<=c<96 -> fp16 Ch=dt row-major at col c-32)
// EPI 3: delta (softplus(v+bias) -> Cf = dtt TIME-MAJOR fp32)
// EPI 4: out   (Cf plain row-major fp32)
template<int EPI, int CONV>
__global__ __launch_bounds__(256, 2)
void tc_gemm(const h16* __restrict__ A, int lda,
             const h16* __restrict__ B, int ldb,
             float* __restrict__ Cf, h16* __restrict__ Ch, h16* __restrict__ Ch2,
             int Nn, int Kk, const float* __restrict__ bias)
{
    extern __shared__ __align__(16) char smem[];
    const unsigned smb = (unsigned)__cvta_generic_to_shared(smem);

    const int tid  = threadIdx.x;
    const int col0 = blockIdx.x * BN;
    const int row0 = blockIdx.y * BM;
    const int grp  = CONV ? (col0 >> 10) : 0;
    const int warp = tid >> 5;
    const int lane = tid & 31;
    const int gid  = lane >> 2;
    const int tig  = lane & 3;
    const int wm0  = (warp & 3) * 32;
    const int wn0  = (warp >> 2) * 64;
    const int sel  = lane >> 3;
    const int lr   = lane & 7;

    auto ld_tile = [&](int kt, int stage) {
        char* base = smem + stage * STAGE_B;
#pragma unroll
        for (int i = 0; i < 2; i++) {
            int q = tid + i * 256;
            int m = q >> 2, j = (q & 3) * 8;
            char* dst = base + m * ROW_B + j * 2;
            const h16* src;
            bool valid = true;
            if (CONV) {
                int tap = kt >> 10, ci0 = kt & 1023, shift = 2 * (3 - tap);
                int rs = row0 + m - shift;
                valid = rs >= 0;
                src = A + (size_t)(valid ? rs : 0) * lda + grp * 1024 + ci0 + j;
            } else {
                src = A + (size_t)(row0 + m) * lda + kt + j;
            }
            cp16(dst, src, valid);
        }
#pragma unroll
        for (int i = 0; i < 2; i++) {
            int q = tid + i * 256;
            int n = q >> 2, j = (q & 3) * 8;
            cp16(base + ARR_B + n * ROW_B + j * 2,
                 B + (size_t)(col0 + n) * ldb + kt + j, true);
        }
        CP_COMMIT();
    };

    float acc[2][8][4];
#pragma unroll
    for (int mt = 0; mt < 2; mt++)
#pragma unroll
        for (int nt = 0; nt < 8; nt++)
#pragma unroll
            for (int q = 0; q < 4; q++) acc[mt][nt][q] = 0.f;

    const int T = Kk / BK;
    ld_tile(0, 0);
    if (T > 1) ld_tile(BK, 1);

    for (int t = 0; t < T; t++) {
        const int stage = t % NSTAGE;
        if (t + 1 < T) CP_WAIT(1); else CP_WAIT(0);
        __syncthreads();
        if (t + 2 < T) ld_tile((t + 2) * BK, (t + 2) % NSTAGE);

        const unsigned Abase = smb + stage * STAGE_B;
        const unsigned Bbase = Abase + ARR_B;

#pragma unroll
        for (int c = 0; c < 2; c++) {
            unsigned a[2][4], b[8][2];
#pragma unroll
            for (int mt = 0; mt < 2; mt++) {
                int row  = wm0 + mt * 16 + ((sel & 1) << 3) + lr;
                int wcol = c * 8 + ((sel >> 1) << 2);
                ldm_x4(a[mt], Abase + row * ROW_B + wcol * 4);
            }
#pragma unroll
            for (int pr = 0; pr < 4; pr++) {
                unsigned r4[4];
                int row  = wn0 + pr * 16 + ((sel >> 1) << 3) + lr;
                int wcol = c * 8 + ((sel & 1) << 2);
                ldm_x4(r4, Bbase + row * ROW_B + wcol * 4);
                b[pr * 2][0]     = r4[0]; b[pr * 2][1]     = r4[1];
                b[pr * 2 + 1][0] = r4[2]; b[pr * 2 + 1][1] = r4[3];
            }
#pragma unroll
            for (int mt = 0; mt < 2; mt++)
#pragma unroll
                for (int nt = 0; nt < 8; nt++)
                    mma_f16(acc[mt][nt], a[mt], b[nt]);
        }
        __syncthreads();
    }

    auto epi_store = [&](int r, int c, float v) {
        if (EPI == 0) {
            if (c < HH) Ch[(size_t)r * HH + c] = __float2half_rn(v);
            else        Ch2[TIX(r, c - HH)] = __float2half_rn(v);
        } else if (EPI == 1) {
            v += bias[c]; v = v * sigmoid_f(v);
            h16 hv = __float2half_rn(v);
            Ch[(size_t)r * HH + c] = hv;       // row-major for proj GEMM
            Ch2[TIX(r, c)] = hv;               // time-major for scan
        } else if (EPI == 2) {
            if (c < NN) {
                Cf[TIX(r, c)] = v;             // Bt
            } else if (c < 2 * NN) {
                ((float*)Ch2)[TIX(r, c - NN)] = v;  // Ct
            } else if (c < PROJC) {
                Ch[(size_t)r * RR + (c - 2 * NN)] = __float2half_rn(v);  // dt
            }
        } else if (EPI == 3) {
            v += bias[c];
            v = (v > 20.f) ? v : log1pf(expf(v));
            Cf[TIX(r, c)] = v;                 // dtt time-major
        } else {
            Cf[(size_t)r * FF + c] = v;
        }
    };

#pragma unroll
    for (int mt = 0; mt < 2; mt++) {
        int r = row0 + wm0 + mt * 16 + gid;
#pragma unroll
        for (int nt = 0; nt < 8; nt++) {
            int c = col0 + wn0 + nt * 8 + tig * 2;
            epi_store(r,     c,     acc[mt][nt][0]);
            epi_store(r,     c + 1, acc[mt][nt][1]);
            epi_store(r + 8, c,     acc[mt][nt][2]);
            epi_store(r + 8, c + 1, acc[mt][nt][3]);
        }
    }
}

// ----- selective scan, time-major streams, 4-step blocks, 1-block prefetch --
__global__ __launch_bounds__(256)
void scan_k(const float* __restrict__ dtt, const h16* __restrict__ ut,
            const float* __restrict__ Bt, const float* __restrict__ Ct,
            const float* __restrict__ A_log, const float* __restrict__ D,
            const h16* __restrict__ rest, h16* __restrict__ zh)
{
    const int gtid = blockIdx.x * blockDim.x + threadIdx.x;
    const int hi   = gtid >> 5;          // chain channel = global warp id
    const int lane = threadIdx.x & 31;
    const int b    = lane >> 4;
    const int n    = lane & 15;

    const float A  = -expf(A_log[hi * NN + n]);
    const float Dh = D[hi];

    const float4* dt4 = (const float4*)(dtt  + (size_t)hi * MROWS + b * LL);
    const uint2*  u4  = (const uint2*) (ut   + (size_t)hi * MROWS + b * LL);
    const uint2*  rs4 = (const uint2*) (rest + (size_t)hi * MROWS + b * LL);
    const float4* B4  = (const float4*)(Bt   + (size_t)n  * MROWS + b * LL);
    const float4* C4  = (const float4*)(Ct   + (size_t)n  * MROWS + b * LL);

    float s = 0.f;
    float4 dtN = dt4[0], vBN = B4[0], vCN = C4[0];
    uint2  uN  = u4[0],  rN  = rs4[0];

    for (int tb = 0; tb < LL / 4; tb++) {
        float4 dtC = dtN, vBC = vBN, vCC = vCN;
        uint2  uC  = uN,  rC  = rN;
        if (tb + 1 < LL / 4) {
            dtN = dt4[tb + 1]; vBN = B4[tb + 1]; vCN = C4[tb + 1];
            uN  = u4[tb + 1];  rN  = rs4[tb + 1];
        }

        float uu[4];
        {
            __half2 lo = *(__half2*)&uC.x, hh = *(__half2*)&uC.y;
            uu[0] = __low2float(lo); uu[1] = __high2float(lo);
            uu[2] = __low2float(hh); uu[3] = __high2float(hh);
        }
        const float dts[4] = {dtC.x, dtC.y, dtC.z, dtC.w};
        const float Bv [4] = {vBC.x, vBC.y, vBC.z, vBC.w};
        const float Cv [4] = {vCC.x, vCC.y, vCC.z, vCC.w};

        float p[4];
#pragma unroll
        for (int j = 0; j < 4; j++) {
            float dt = fminf(fmaxf(dts[j], 0.001f), 0.1f);
            s = __expf(dt * A) * s + (dt * uu[j]) * Bv[j];
            p[j] = Cv[j] * s;
        }
        // 4 interleaved 16-lane reductions
#pragma unroll
        for (int m = 1; m < 16; m <<= 1) {
#pragma unroll
            for (int j = 0; j < 4; j++)
                p[j] += __shfl_xor_sync(0xffffffffu, p[j], m);
        }

        if (n == 0) {
            float rv[4];
            __half2 lo = *(__half2*)&rC.x, hh = *(__half2*)&rC.y;
            rv[0] = __low2float(lo); rv[1] = __high2float(lo);
            rv[2] = __low2float(hh); rv[3] = __high2float(hh);
#pragma unroll
            for (int j = 0; j < 4; j++) {
                int t = tb * 4 + j;
                float yv = p[j] + uu[j] * Dh;
                float zv = yv * (rv[j] * sigmoid_f(rv[j]));
                zh[(size_t)(t * BB + b) * HH + hi] = __float2half_rn(zv);
            }
        }
    }
}

// ---------------- launch ---------------------------------------------------
extern "C" void kernel_launch(void* const* d_in, const int* in_sizes, int n_in,
                              void* d_out, int out_size)
{
    const float* x      = (const float*)d_in[0];
    const float* W_in   = (const float*)d_in[1];
    const float* W_conv = (const float*)d_in[2];
    const float* b_conv = (const float*)d_in[3];
    const float* A_log  = (const float*)d_in[4];
    const float* D      = (const float*)d_in[5];
    const float* W_ssm  = (const float*)d_in[6];
    const float* W_dt   = (const float*)d_in[7];
    const float* b_dt   = (const float*)d_in[8];
    const float* W_out  = (const float*)d_in[9];
    float* out = (float*)d_out;

    void* p;
#define SYM(v, s) cudaGetSymbolAddress(&p, s); auto* v = decltype(&s[0])(p)
    SYM(xh, g_xh);   SYM(Win, g_Win);
    SYM(xs, g_xs);   SYM(Wc, g_Wc);
    SYM(uh, g_uh);   SYM(Ws, g_Ws);
    SYM(dth, g_dth); SYM(Wd, g_Wd);
    SYM(zh, g_zh);   SYM(Wo, g_Wo);
    SYM(dtt, g_dtt); SYM(ut, g_ut); SYM(rest, g_rest);
    SYM(Btp, g_Bt);  SYM(Ctp, g_Ct);
#undef SYM

    cudaFuncSetAttribute(tc_gemm<0,0>, cudaFuncAttributeMaxDynamicSharedMemorySize, SMEM_TOTAL);
    cudaFuncSetAttribute(tc_gemm<1,1>, cudaFuncAttributeMaxDynamicSharedMemorySize, SMEM_TOTAL);
    cudaFuncSetAttribute(tc_gemm<2,0>, cudaFuncAttributeMaxDynamicSharedMemorySize, SMEM_TOTAL);
    cudaFuncSetAttribute(tc_gemm<3,0>, cudaFuncAttributeMaxDynamicSharedMemorySize, SMEM_TOTAL);
    cudaFuncSetAttribute(tc_gemm<4,0>, cudaFuncAttributeMaxDynamicSharedMemorySize, SMEM_TOTAL);

    dim3 blk(256);
    dim3 tblk(32, 8);

    // 1) x -> fp16 AND W_conv transpose (fused)
    cvt1_k<<<8192 + 8192, tblk>>>(x, xh, W_conv, Wc);

    // 2) W_in transpose
    trhalf_k<<<dim3(FF / 32, (2 * HH) / 32), tblk>>>(W_in, Win, FF, 2 * HH, 2 * HH);

    // 3) h = x @ W_in : xs -> fp16 g_xs, res -> h16 time-major g_rest
    tc_gemm<0, 0><<<dim3(2 * HH / BN, MROWS / BM), blk, SMEM_TOTAL>>>(
        xh, FF, Win, FF, nullptr, xs, rest, 2 * HH, FF, nullptr);

    // 4) u = silu(conv(xs) + b_conv) -> fp16 g_uh + time-major g_ut  [ncu slot]
    tc_gemm<1, 1><<<dim3(HH / BN, MROWS / BM), blk, SMEM_TOTAL>>>(
        xs, HH, Wc, KK * 1024, nullptr, uh, ut, HH, KK * 1024, b_conv);

    // 5) transpose W_ssm / W_dt / W_out
    tr3_k<<<256 + 128 + 2048, tblk>>>(W_ssm, Ws, W_dt, Wd, W_out, Wo);

    // 6) proj: Bt/Ct time-major fp32, dt cols -> fp16 g_dth
    tc_gemm<2, 0><<<dim3(1, MROWS / BM), blk, SMEM_TOTAL>>>(
        uh, HH, Ws, HH, Btp, dth, (h16*)Ctp, PROJC, HH, nullptr);

    // 7) delta = softplus(dt @ W_dt + b_dt) -> fp32 time-major g_dtt
    tc_gemm<3, 0><<<dim3(HH / BN, MROWS / BM), blk, SMEM_TOTAL>>>(
        dth, RR, Wd, RR, dtt, nullptr, nullptr, HH, RR, b_dt);

    // 8) selective scan (time-major streams) -> fp16 g_zh
    scan_k<<<BB * HH * NN / 256, blk>>>(dtt, ut, Btp, Ctp, A_log, D, rest, zh);

    // 9) out = z @ W_out -> fp32 out
    tc_gemm<4, 0><<<dim3(FF / BN, MROWS / BM), blk, SMEM_TOTAL>>>(
        zh, HH, Wo, HH, out, nullptr, nullptr, FF, HH, nullptr);
}

// round 15
// speedup vs baseline: 2.4047x; 1.1191x over previous
#include <cuda_runtime.h>
#include <cuda_fp16.h>
#include <cstdint>
#include <math.h>

// Problem constants
#define LL 1024
#define BB 2
#define FF 1024
#define HH 2048
#define NN 16
#define RR 64
#define KK 4
#define MROWS (LL*BB)        // 2048
#define PROJC (RR + 2*NN)    // 96

typedef __half h16;

// ---------------- scratch (device globals: allocation-free) ----------------
__device__ h16 g_xh [(size_t)MROWS * FF];
__device__ h16 g_Win[(size_t)(2*HH) * FF];      // [4096][1024] K-major
__device__ h16 g_xs [(size_t)MROWS * HH];
__device__ h16 g_Wc [(size_t)HH * (KK*1024)];   // [2048][4096]
__device__ h16 g_uh [(size_t)MROWS * HH];       // u row-major (proj GEMM A)
__device__ h16 g_Ws [(size_t)128 * HH];         // [128 pad][2048]
__device__ h16 g_dth[(size_t)MROWS * RR];
__device__ h16 g_Wd [(size_t)HH * RR];          // [2048][64]
__device__ h16 g_zh [(size_t)MROWS * HH];
__device__ h16 g_Wo [(size_t)FF * HH];          // [1024][2048]
// time-major scan inputs: [channel][b][t]
__device__ float g_dtt [(size_t)HH * MROWS];    // delta  [hi][b][t]
__device__ h16   g_ut  [(size_t)HH * MROWS];    // u      [hi][b][t]
__device__ h16   g_rest[(size_t)HH * MROWS];    // res    [hi][b][t]
__device__ float g_Bt  [(size_t)NN * MROWS];    // B      [n][b][t]
__device__ float g_Ct  [(size_t)NN * MROWS];    // C      [n][b][t]

// transposed (time-major) index for scan tensors: r = t*2+b
#define TIX(r, c) ((size_t)(c) * MROWS + ((r) & 1) * LL + ((r) >> 1))

// ---------------- tiling ----------------------------------------------------
#define BM 128
#define BN 128
#define BK 64
#define ROW_B   144                       // 64 halves (128B) + 16B pad
#define ARR_B   (128 * ROW_B)             // 18432 B per operand tile
#define STAGE_B (2 * ARR_B)               // A + B = 36864 B
#define NSTAGE  3
#define SMEM_TOTAL (NSTAGE * STAGE_B)     // 110592 B

__device__ __forceinline__ float sigmoid_f(float x) {
    return 1.f / (1.f + __expf(-x));
}
__device__ __forceinline__ void mma_f16(float* d, const unsigned* a, const unsigned* b) {
    asm volatile(
        "mma.sync.aligned.m16n8k16.row.col.f32.f16.f16.f32 "
        "{%0,%1,%2,%3}, {%4,%5,%6,%7}, {%8,%9}, {%0,%1,%2,%3};\n"
        : "+f"(d[0]), "+f"(d[1]), "+f"(d[2]), "+f"(d[3])
        : "r"(a[0]), "r"(a[1]), "r"(a[2]), "r"(a[3]), "r"(b[0]), "r"(b[1]));
}
__device__ __forceinline__ void ldm_x4(unsigned* r, unsigned saddr) {
    asm volatile("ldmatrix.sync.aligned.m8n8.x4.shared.b16 {%0,%1,%2,%3}, [%4];"
        : "=r"(r[0]), "=r"(r[1]), "=r"(r[2]), "=r"(r[3]) : "r"(saddr));
}
__device__ __forceinline__ void cp16(void* smem_dst, const void* gsrc, bool valid) {
    unsigned s = (unsigned)__cvta_generic_to_shared(smem_dst);
    int sz = valid ? 16 : 0;
    asm volatile("cp.async.cg.shared.global [%0], [%1], 16, %2;\n"
                 :: "r"(s), "l"(gsrc), "r"(sz));
}
#define CP_COMMIT() asm volatile("cp.async.commit_group;\n")
#define CP_WAIT(n)  asm volatile("cp.async.wait_group %0;\n" :: "n"(n))

// ---------------- pre-passes -------------------------------------------------
__device__ __forceinline__ void tr_body(const float* __restrict__ in,
                                        h16* __restrict__ o,
                                        int Kd, int Nd, int Npad,
                                        int k0, int n0)
{
    __shared__ float tile[32][33];
    for (int i = threadIdx.y; i < 32; i += 8) {
        int k = k0 + i, n = n0 + threadIdx.x;
        tile[i][threadIdx.x] = (k < Kd && n < Nd) ? in[(size_t)k * Nd + n] : 0.f;
    }
    __syncthreads();
    for (int i = threadIdx.y; i < 32; i += 8) {
        int n = n0 + i, k = k0 + threadIdx.x;
        if (n < Npad && k < Kd)
            o[(size_t)n * Kd + k] = __float2half_rn(tile[threadIdx.x][i]);
    }
}

// launch 1: blocks [0,8192): tohalf(x); blocks [8192, 16384): trhalf(W_conv)
__global__ void cvt1_k(const float* __restrict__ x, h16* __restrict__ xh,
                       const float* __restrict__ Wc_in, h16* __restrict__ Wc_o)
{
    int bid = blockIdx.x;
    int t = threadIdx.y * 32 + threadIdx.x;
    if (bid < 8192) {
        int i = bid * 256 + t;
        if (i < MROWS * FF) xh[i] = __float2half_rn(x[i]);
    } else {
        int b2 = bid - 8192;
        int kb = b2 & 127, nb = b2 >> 7;
        tr_body(Wc_in, Wc_o, KK * 1024, HH, HH, kb * 32, nb * 32);
    }
}

__global__ void trhalf_k(const float* __restrict__ in, h16* __restrict__ o,
                         int Kd, int Nd, int Npad)
{
    tr_body(in, o, Kd, Nd, Npad, blockIdx.x * 32, blockIdx.y * 32);
}

__global__ void tr3_k(const float* __restrict__ Ws_in, h16* __restrict__ Ws_o,
                      const float* __restrict__ Wd_in, h16* __restrict__ Wd_o,
                      const float* __restrict__ Wo_in, h16* __restrict__ Wo_o)
{
    int bid = blockIdx.x;
    if (bid < 256) {            // W_ssm
        int kb = bid & 63, nb = bid >> 6;
        tr_body(Ws_in, Ws_o, HH, PROJC, 128, kb * 32, nb * 32);
    } else if (bid < 384) {     // W_dt
        int b2 = bid - 256;
        int kb = b2 & 1, nb = b2 >> 1;
        tr_body(Wd_in, Wd_o, RR, HH, HH, kb * 32, nb * 32);
    } else {                    // W_out
        int b2 = bid - 384;
        int kb = b2 & 63, nb = b2 >> 6;
        tr_body(Wo_in, Wo_o, HH, FF, FF, kb * 32, nb * 32);
    }
}

// ===== fp16 tensor GEMM: 128x128x64 tile, 256 thr (8 warps, 32x64/warp) ====
// EPI 0: GEMM1 (c<HH -> fp16 Ch=xs; else h16 Ch2 = res TIME-MAJOR)
// EPI 1: conv  (silu(v+bias) -> fp16 Ch=u row-major AND Ch2=u time-major)
// EPI 2: proj  (c<16->Bt tm fp32 via Cf; c<32->Ct tm fp32 via Ch2-cast;
//               32<=c<96 -> fp16 Ch=dt row-major at col c-32)
// EPI 3: delta (softplus(v+bias) -> Cf = dtt TIME-MAJOR fp32)
// EPI 4: out   (Cf plain row-major fp32)
template<int EPI, int CONV>
__global__ __launch_bounds__(256, 2)
void tc_gemm(const h16* __restrict__ A, int lda,
             const h16* __restrict__ B, int ldb,
             float* __restrict__ Cf, h16* __restrict__ Ch, h16* __restrict__ Ch2,
             int Nn, int Kk, const float* __restrict__ bias)
{
    extern __shared__ __align__(16) char smem[];
    const unsigned smb = (unsigned)__cvta_generic_to_shared(smem);

    const int tid  = threadIdx.x;
    const int col0 = blockIdx.x * BN;
    const int row0 = blockIdx.y * BM;
    const int grp  = CONV ? (col0 >> 10) : 0;
    const int warp = tid >> 5;
    const int lane = tid & 31;
    const int gid  = lane >> 2;
    const int tig  = lane & 3;
    const int wm0  = (warp & 3) * 32;
    const int wn0  = (warp >> 2) * 64;
    const int sel  = lane >> 3;
    const int lr   = lane & 7;

    auto ld_tile = [&](int kt, int stage) {
        char* base = smem + stage * STAGE_B;
        // A: 128 rows x 64 halves = 1024 x 16B chunks, 4 per thread
#pragma unroll
        for (int i = 0; i < 4; i++) {
            int q = tid + i * 256;
            int m = q >> 3, j = (q & 7) * 8;     // row, half-offset
            char* dst = base + m * ROW_B + j * 2;
            const h16* src;
            bool valid = true;
            if (CONV) {
                int tap = kt >> 10, ci0 = kt & 1023, shift = 2 * (3 - tap);
                int rs = row0 + m - shift;
                valid = rs >= 0;
                src = A + (size_t)(valid ? rs : 0) * lda + grp * 1024 + ci0 + j;
            } else {
                src = A + (size_t)(row0 + m) * lda + kt + j;
            }
            cp16(dst, src, valid);
        }
#pragma unroll
        for (int i = 0; i < 4; i++) {
            int q = tid + i * 256;
            int n = q >> 3, j = (q & 7) * 8;
            cp16(base + ARR_B + n * ROW_B + j * 2,
                 B + (size_t)(col0 + n) * ldb + kt + j, true);
        }
        CP_COMMIT();
    };

    float acc[2][8][4];
#pragma unroll
    for (int mt = 0; mt < 2; mt++)
#pragma unroll
        for (int nt = 0; nt < 8; nt++)
#pragma unroll
            for (int q = 0; q < 4; q++) acc[mt][nt][q] = 0.f;

    const int T = Kk / BK;
    ld_tile(0, 0);
    if (T > 1) ld_tile(BK, 1);

    for (int t = 0; t < T; t++) {
        const int stage = t % NSTAGE;
        if (t + 1 < T) CP_WAIT(1); else CP_WAIT(0);
        __syncthreads();
        if (t + 2 < T) ld_tile((t + 2) * BK, (t + 2) % NSTAGE);

        const unsigned Abase = smb + stage * STAGE_B;
        const unsigned Bbase = Abase + ARR_B;

#pragma unroll
        for (int c = 0; c < 4; c++) {             // four k16 chunks
            unsigned a[2][4], b[8][2];
#pragma unroll
            for (int mt = 0; mt < 2; mt++) {
                int row  = wm0 + mt * 16 + ((sel & 1) << 3) + lr;
                int wcol = c * 8 + ((sel >> 1) << 2);
                ldm_x4(a[mt], Abase + row * ROW_B + wcol * 4);
            }
#pragma unroll
            for (int pr = 0; pr < 4; pr++) {
                unsigned r4[4];
                int row  = wn0 + pr * 16 + ((sel >> 1) << 3) + lr;
                int wcol = c * 8 + ((sel & 1) << 2);
                ldm_x4(r4, Bbase + row * ROW_B + wcol * 4);
                b[pr * 2][0]     = r4[0]; b[pr * 2][1]     = r4[1];
                b[pr * 2 + 1][0] = r4[2]; b[pr * 2 + 1][1] = r4[3];
            }
#pragma unroll
            for (int mt = 0; mt < 2; mt++)
#pragma unroll
                for (int nt = 0; nt < 8; nt++)
                    mma_f16(acc[mt][nt], a[mt], b[nt]);
        }
        __syncthreads();
    }

    auto epi_store = [&](int r, int c, float v) {
        if (EPI == 0) {
            if (c < HH) Ch[(size_t)r * HH + c] = __float2half_rn(v);
            else        Ch2[TIX(r, c - HH)] = __float2half_rn(v);
        } else if (EPI == 1) {
            v += bias[c]; v = v * sigmoid_f(v);
            h16 hv = __float2half_rn(v);
            Ch[(size_t)r * HH + c] = hv;       // row-major for proj GEMM
            Ch2[TIX(r, c)] = hv;               // time-major for scan
        } else if (EPI == 2) {
            if (c < NN) {
                Cf[TIX(r, c)] = v;             // Bt
            } else if (c < 2 * NN) {
                ((float*)Ch2)[TIX(r, c - NN)] = v;  // Ct
            } else if (c < PROJC) {
                Ch[(size_t)r * RR + (c - 2 * NN)] = __float2half_rn(v);  // dt
            }
        } else if (EPI == 3) {
            v += bias[c];
            v = (v > 20.f) ? v : log1pf(expf(v));
            Cf[TIX(r, c)] = v;                 // dtt time-major
        } else {
            Cf[(size_t)r * FF + c] = v;
        }
    };

#pragma unroll
    for (int mt = 0; mt < 2; mt++) {
        int r = row0 + wm0 + mt * 16 + gid;
#pragma unroll
        for (int nt = 0; nt < 8; nt++) {
            int c = col0 + wn0 + nt * 8 + tig * 2;
            epi_store(r,     c,     acc[mt][nt][0]);
            epi_store(r,     c + 1, acc[mt][nt][1]);
            epi_store(r + 8, c,     acc[mt][nt][2]);
            epi_store(r + 8, c + 1, acc[mt][nt][3]);
        }
    }
}

// ----- selective scan, time-major streams, 4-step blocks, 1-block prefetch --
__global__ __launch_bounds__(256)
void scan_k(const float* __restrict__ dtt, const h16* __restrict__ ut,
            const float* __restrict__ Bt, const float* __restrict__ Ct,
            const float* __restrict__ A_log, const float* __restrict__ D,
            const h16* __restrict__ rest, h16* __restrict__ zh)
{
    const int gtid = blockIdx.x * blockDim.x + threadIdx.x;
    const int hi   = gtid >> 5;          // chain channel = global warp id
    const int lane = threadIdx.x & 31;
    const int b    = lane >> 4;
    const int n    = lane & 15;

    const float A  = -expf(A_log[hi * NN + n]);
    const float Dh = D[hi];

    const float4* dt4 = (const float4*)(dtt  + (size_t)hi * MROWS + b * LL);
    const uint2*  u4  = (const uint2*) (ut   + (size_t)hi * MROWS + b * LL);
    const uint2*  rs4 = (const uint2*) (rest + (size_t)hi * MROWS + b * LL);
    const float4* B4  = (const float4*)(Bt   + (size_t)n  * MROWS + b * LL);
    const float4* C4  = (const float4*)(Ct   + (size_t)n  * MROWS + b * LL);

    float s = 0.f;
    float4 dtN = dt4[0], vBN = B4[0], vCN = C4[0];
    uint2  uN  = u4[0],  rN  = rs4[0];

    for (int tb = 0; tb < LL / 4; tb++) {
        float4 dtC = dtN, vBC = vBN, vCC = vCN;
        uint2  uC  = uN,  rC  = rN;
        if (tb + 1 < LL / 4) {
            dtN = dt4[tb + 1]; vBN = B4[tb + 1]; vCN = C4[tb + 1];
            uN  = u4[tb + 1];  rN  = rs4[tb + 1];
        }

        float uu[4];
        {
            __half2 lo = *(__half2*)&uC.x, hh = *(__half2*)&uC.y;
            uu[0] = __low2float(lo); uu[1] = __high2float(lo);
            uu[2] = __low2float(hh); uu[3] = __high2float(hh);
        }
        const float dts[4] = {dtC.x, dtC.y, dtC.z, dtC.w};
        const float Bv [4] = {vBC.x, vBC.y, vBC.z, vBC.w};
        const float Cv [4] = {vCC.x, vCC.y, vCC.z, vCC.w};

        float p[4];
#pragma unroll
        for (int j = 0; j < 4; j++) {
            float dt = fminf(fmaxf(dts[j], 0.001f), 0.1f);
            s = __expf(dt * A) * s + (dt * uu[j]) * Bv[j];
            p[j] = Cv[j] * s;
        }
        // 4 interleaved 16-lane reductions (sum lands in every lane)
#pragma unroll
        for (int m = 1; m < 16; m <<= 1) {
#pragma unroll
            for (int j = 0; j < 4; j++)
                p[j] += __shfl_xor_sync(0xffffffffu, p[j], m);
        }

        if (n < 4) {                 // lane n stores timestep tb*4+n
            float rv;
            {
                __half2 lo = *(__half2*)&rC.x, hh = *(__half2*)&rC.y;
                float r4v[4] = {__low2float(lo), __high2float(lo),
                                __low2float(hh), __high2float(hh)};
                rv = r4v[n];
            }
            int t = tb * 4 + n;
            float yv = p[n] + uu[n] * Dh;
            float zv = yv * (rv * sigmoid_f(rv));
            zh[(size_t)(t * BB + b) * HH + hi] = __float2half_rn(zv);
        }
    }
}

// ---------------- launch ---------------------------------------------------
extern "C" void kernel_launch(void* const* d_in, const int* in_sizes, int n_in,
                              void* d_out, int out_size)
{
    const float* x      = (const float*)d_in[0];
    const float* W_in   = (const float*)d_in[1];
    const float* W_conv = (const float*)d_in[2];
    const float* b_conv = (const float*)d_in[3];
    const float* A_log  = (const float*)d_in[4];
    const float* D      = (const float*)d_in[5];
    const float* W_ssm  = (const float*)d_in[6];
    const float* W_dt   = (const float*)d_in[7];
    const float* b_dt   = (const float*)d_in[8];
    const float* W_out  = (const float*)d_in[9];
    float* out = (float*)d_out;

    void* p;
#define SYM(v, s) cudaGetSymbolAddress(&p, s); auto* v = decltype(&s[0])(p)
    SYM(xh, g_xh);   SYM(Win, g_Win);
    SYM(xs, g_xs);   SYM(Wc, g_Wc);
    SYM(uh, g_uh);   SYM(Ws, g_Ws);
    SYM(dth, g_dth); SYM(Wd, g_Wd);
    SYM(zh, g_zh);   SYM(Wo, g_Wo);
    SYM(dtt, g_dtt); SYM(ut, g_ut); SYM(rest, g_rest);
    SYM(Btp, g_Bt);  SYM(Ctp, g_Ct);
#undef SYM

    cudaFuncSetAttribute(tc_gemm<0,0>, cudaFuncAttributeMaxDynamicSharedMemorySize, SMEM_TOTAL);
    cudaFuncSetAttribute(tc_gemm<1,1>, cudaFuncAttributeMaxDynamicSharedMemorySize, SMEM_TOTAL);
    cudaFuncSetAttribute(tc_gemm<2,0>, cudaFuncAttributeMaxDynamicSharedMemorySize, SMEM_TOTAL);
    cudaFuncSetAttribute(tc_gemm<3,0>, cudaFuncAttributeMaxDynamicSharedMemorySize, SMEM_TOTAL);
    cudaFuncSetAttribute(tc_gemm<4,0>, cudaFuncAttributeMaxDynamicSharedMemorySize, SMEM_TOTAL);

    dim3 blk(256);
    dim3 tblk(32, 8);

    // 1) x -> fp16 AND W_conv transpose (fused)
    cvt1_k<<<8192 + 8192, tblk>>>(x, xh, W_conv, Wc);

    // 2) W_in transpose
    trhalf_k<<<dim3(FF / 32, (2 * HH) / 32), tblk>>>(W_in, Win, FF, 2 * HH, 2 * HH);

    // 3) h = x @ W_in : xs -> fp16 g_xs, res -> h16 time-major g_rest
    tc_gemm<0, 0><<<dim3(2 * HH / BN, MROWS / BM), blk, SMEM_TOTAL>>>(
        xh, FF, Win, FF, nullptr, xs, rest, 2 * HH, FF, nullptr);

    // 4) u = silu(conv(xs) + b_conv) -> fp16 g_uh + time-major g_ut  [ncu slot]
    tc_gemm<1, 1><<<dim3(HH / BN, MROWS / BM), blk, SMEM_TOTAL>>>(
        xs, HH, Wc, KK * 1024, nullptr, uh, ut, HH, KK * 1024, b_conv);

    // 5) transpose W_ssm / W_dt / W_out
    tr3_k<<<256 + 128 + 2048, tblk>>>(W_ssm, Ws, W_dt, Wd, W_out, Wo);

    // 6) proj: Bt/Ct time-major fp32, dt cols -> fp16 g_dth
    tc_gemm<2, 0><<<dim3(1, MROWS / BM), blk, SMEM_TOTAL>>>(
        uh, HH, Ws, HH, Btp, dth, (h16*)Ctp, PROJC, HH, nullptr);

    // 7) delta = softplus(dt @ W_dt + b_dt) -> fp32 time-major g_dtt
    tc_gemm<3, 0><<<dim3(HH / BN, MROWS / BM), blk, SMEM_TOTAL>>>(
        dth, RR, Wd, RR, dtt, nullptr, nullptr, HH, RR, b_dt);

    // 8) selective scan (time-major streams) -> fp16 g_zh
    scan_k<<<BB * HH * NN / 256, blk>>>(dtt, ut, Btp, Ctp, A_log, D, rest, zh);

    // 9) out = z @ W_out -> fp32 out
    tc_gemm<4, 0><<<dim3(FF / BN, MROWS / BM), blk, SMEM_TOTAL>>>(
        zh, HH, Wo, HH, out, nullptr, nullptr, FF, HH, nullptr);
}

// round 16
// speedup vs baseline: 2.4250x; 1.0084x over previous
#include <cuda_runtime.h>
#include <cuda_fp16.h>
#include <cstdint>
#include <math.h>

// Problem constants
#define LL 1024
#define BB 2
#define FF 1024
#define HH 2048
#define NN 16
#define RR 64
#define KK 4
#define MROWS (LL*BB)        // 2048
#define PROJC (RR + 2*NN)    // 96
#define TC 128               // scan chunk length
#define NCH 8                // scan chunks
#define KSPL 8               // proj split-K ways

typedef __half h16;

// ---------------- scratch (device globals: allocation-free) ----------------
__device__ h16 g_xh [(size_t)MROWS * FF];
__device__ h16 g_Win[(size_t)(2*HH) * FF];      // [4096][1024] K-major
__device__ h16 g_xs [(size_t)MROWS * HH];
__device__ h16 g_Wc [(size_t)HH * (KK*1024)];   // [2048][4096]
__device__ h16 g_uh [(size_t)MROWS * HH];       // u row-major (proj GEMM A)
__device__ h16 g_Ws [(size_t)128 * HH];         // [128 pad][2048]
__device__ h16 g_dth[(size_t)MROWS * RR];
__device__ h16 g_Wd [(size_t)HH * RR];          // [2048][64]
__device__ h16 g_zh [(size_t)MROWS * HH];
__device__ h16 g_Wo [(size_t)FF * HH];          // [1024][2048]
// time-major scan inputs: [channel][b][t]
__device__ float g_dtt [(size_t)HH * MROWS];    // delta  [hi][b][t]
__device__ h16   g_ut  [(size_t)HH * MROWS];    // u      [hi][b][t]
__device__ h16   g_rest[(size_t)HH * MROWS];    // res    [hi][b][t]
__device__ float g_Bt  [(size_t)NN * MROWS];    // B      [n][b][t]
__device__ float g_Ct  [(size_t)NN * MROWS];    // C      [n][b][t]
// chunked-scan intermediates: chain = hi*BB+b; [chain][ch][n]
__device__ float g_loc [(size_t)HH * BB * NCH * 16];
__device__ float g_pA  [(size_t)HH * BB * NCH * 16];
__device__ float g_init[(size_t)HH * BB * NCH * 16];
// proj split-K partials [split][r][128]
__device__ float g_pp  [(size_t)KSPL * MROWS * 128];

// transposed (time-major) index for scan tensors: r = t*2+b
#define TIX(r, c) ((size_t)(c) * MROWS + ((r) & 1) * LL + ((r) >> 1))
#define LOC(chain, ch, n) (((size_t)(chain) * NCH + (ch)) * 16 + (n))

// ---------------- tiling ----------------------------------------------------
#define BM 128
#define BN 128
#define BK 64
#define ROW_B   144                       // 64 halves (128B) + 16B pad
#define ARR_B   (128 * ROW_B)             // 18432 B per operand tile
#define STAGE_B (2 * ARR_B)               // A + B = 36864 B
#define NSTAGE  3
#define SMEM_TOTAL (NSTAGE * STAGE_B)     // 110592 B

__device__ __forceinline__ float sigmoid_f(float x) {
    return 1.f / (1.f + __expf(-x));
}
__device__ __forceinline__ void mma_f16(float* d, const unsigned* a, const unsigned* b) {
    asm volatile(
        "mma.sync.aligned.m16n8k16.row.col.f32.f16.f16.f32 "
        "{%0,%1,%2,%3}, {%4,%5,%6,%7}, {%8,%9}, {%0,%1,%2,%3};\n"
        : "+f"(d[0]), "+f"(d[1]), "+f"(d[2]), "+f"(d[3])
        : "r"(a[0]), "r"(a[1]), "r"(a[2]), "r"(a[3]), "r"(b[0]), "r"(b[1]));
}
__device__ __forceinline__ void ldm_x4(unsigned* r, unsigned saddr) {
    asm volatile("ldmatrix.sync.aligned.m8n8.x4.shared.b16 {%0,%1,%2,%3}, [%4];"
        : "=r"(r[0]), "=r"(r[1]), "=r"(r[2]), "=r"(r[3]) : "r"(saddr));
}
__device__ __forceinline__ void cp16(void* smem_dst, const void* gsrc, bool valid) {
    unsigned s = (unsigned)__cvta_generic_to_shared(smem_dst);
    int sz = valid ? 16 : 0;
    asm volatile("cp.async.cg.shared.global [%0], [%1], 16, %2;\n"
                 :: "r"(s), "l"(gsrc), "r"(sz));
}
#define CP_COMMIT() asm volatile("cp.async.commit_group;\n")
#define CP_WAIT(n)  asm volatile("cp.async.wait_group %0;\n" :: "n"(n))

// ---------------- pre-passes -------------------------------------------------
__device__ __forceinline__ void tr_body(const float* __restrict__ in,
                                        h16* __restrict__ o,
                                        int Kd, int Nd, int Npad,
                                        int k0, int n0)
{
    __shared__ float tile[32][33];
    for (int i = threadIdx.y; i < 32; i += 8) {
        int k = k0 + i, n = n0 + threadIdx.x;
        tile[i][threadIdx.x] = (k < Kd && n < Nd) ? in[(size_t)k * Nd + n] : 0.f;
    }
    __syncthreads();
    for (int i = threadIdx.y; i < 32; i += 8) {
        int n = n0 + i, k = k0 + threadIdx.x;
        if (n < Npad && k < Kd)
            o[(size_t)n * Kd + k] = __float2half_rn(tile[threadIdx.x][i]);
    }
}

__global__ void cvt1_k(const float* __restrict__ x, h16* __restrict__ xh,
                       const float* __restrict__ Wc_in, h16* __restrict__ Wc_o)
{
    int bid = blockIdx.x;
    int t = threadIdx.y * 32 + threadIdx.x;
    if (bid < 8192) {
        int i = bid * 256 + t;
        if (i < MROWS * FF) xh[i] = __float2half_rn(x[i]);
    } else {
        int b2 = bid - 8192;
        int kb = b2 & 127, nb = b2 >> 7;
        tr_body(Wc_in, Wc_o, KK * 1024, HH, HH, kb * 32, nb * 32);
    }
}

__global__ void trhalf_k(const float* __restrict__ in, h16* __restrict__ o,
                         int Kd, int Nd, int Npad)
{
    tr_body(in, o, Kd, Nd, Npad, blockIdx.x * 32, blockIdx.y * 32);
}

__global__ void tr3_k(const float* __restrict__ Ws_in, h16* __restrict__ Ws_o,
                      const float* __restrict__ Wd_in, h16* __restrict__ Wd_o,
                      const float* __restrict__ Wo_in, h16* __restrict__ Wo_o)
{
    int bid = blockIdx.x;
    if (bid < 256) {            // W_ssm
        int kb = bid & 63, nb = bid >> 6;
        tr_body(Ws_in, Ws_o, HH, PROJC, 128, kb * 32, nb * 32);
    } else if (bid < 384) {     // W_dt
        int b2 = bid - 256;
        int kb = b2 & 1, nb = b2 >> 1;
        tr_body(Wd_in, Wd_o, RR, HH, HH, kb * 32, nb * 32);
    } else {                    // W_out
        int b2 = bid - 384;
        int kb = b2 & 63, nb = b2 >> 6;
        tr_body(Wo_in, Wo_o, HH, FF, FF, kb * 32, nb * 32);
    }
}

// ===== fp16 tensor GEMM: 128x128x64 tile, 256 thr (8 warps, 32x64/warp) ====
// EPI 0: GEMM1 (c<HH -> fp16 Ch=xs; else h16 Ch2 = res TIME-MAJOR)
// EPI 1: conv  (silu(v+bias) -> fp16 Ch=u row-major AND Ch2=u time-major)
// EPI 3: delta (softplus(v+bias) -> Cf = dtt TIME-MAJOR fp32)
// EPI 4: out   (Cf plain row-major fp32)
// EPI 5: split-K partial (Cf[r*128+c], SPLITK=1)
template<int EPI, int CONV, int SPLITK>
__global__ __launch_bounds__(256, 2)
void tc_gemm(const h16* __restrict__ A, int lda,
             const h16* __restrict__ B, int ldb,
             float* __restrict__ Cf, h16* __restrict__ Ch, h16* __restrict__ Ch2,
             int Nn, int Kk, const float* __restrict__ bias)
{
    extern __shared__ __align__(16) char smem[];
    const unsigned smb = (unsigned)__cvta_generic_to_shared(smem);

    if (SPLITK) {
        int kb = blockIdx.x * Kk;
        A += kb; B += kb;
        Cf += (size_t)blockIdx.x * MROWS * 128;
    }

    const int tid  = threadIdx.x;
    const int col0 = SPLITK ? 0 : blockIdx.x * BN;
    const int row0 = blockIdx.y * BM;
    const int grp  = CONV ? (col0 >> 10) : 0;
    const int warp = tid >> 5;
    const int lane = tid & 31;
    const int gid  = lane >> 2;
    const int tig  = lane & 3;
    const int wm0  = (warp & 3) * 32;
    const int wn0  = (warp >> 2) * 64;
    const int sel  = lane >> 3;
    const int lr   = lane & 7;

    auto ld_tile = [&](int kt, int stage) {
        char* base = smem + stage * STAGE_B;
#pragma unroll
        for (int i = 0; i < 4; i++) {
            int q = tid + i * 256;
            int m = q >> 3, j = (q & 7) * 8;
            char* dst = base + m * ROW_B + j * 2;
            const h16* src;
            bool valid = true;
            if (CONV) {
                int tap = kt >> 10, ci0 = kt & 1023, shift = 2 * (3 - tap);
                int rs = row0 + m - shift;
                valid = rs >= 0;
                src = A + (size_t)(valid ? rs : 0) * lda + grp * 1024 + ci0 + j;
            } else {
                src = A + (size_t)(row0 + m) * lda + kt + j;
            }
            cp16(dst, src, valid);
        }
#pragma unroll
        for (int i = 0; i < 4; i++) {
            int q = tid + i * 256;
            int n = q >> 3, j = (q & 7) * 8;
            cp16(base + ARR_B + n * ROW_B + j * 2,
                 B + (size_t)(col0 + n) * ldb + kt + j, true);
        }
        CP_COMMIT();
    };

    float acc[2][8][4];
#pragma unroll
    for (int mt = 0; mt < 2; mt++)
#pragma unroll
        for (int nt = 0; nt < 8; nt++)
#pragma unroll
            for (int q = 0; q < 4; q++) acc[mt][nt][q] = 0.f;

    const int T = Kk / BK;
    ld_tile(0, 0);
    if (T > 1) ld_tile(BK, 1);

    for (int t = 0; t < T; t++) {
        const int stage = t % NSTAGE;
        if (t + 1 < T) CP_WAIT(1); else CP_WAIT(0);
        __syncthreads();
        if (t + 2 < T) ld_tile((t + 2) * BK, (t + 2) % NSTAGE);

        const unsigned Abase = smb + stage * STAGE_B;
        const unsigned Bbase = Abase + ARR_B;

#pragma unroll
        for (int c = 0; c < 4; c++) {
            unsigned a[2][4], b[8][2];
#pragma unroll
            for (int mt = 0; mt < 2; mt++) {
                int row  = wm0 + mt * 16 + ((sel & 1) << 3) + lr;
                int wcol = c * 8 + ((sel >> 1) << 2);
                ldm_x4(a[mt], Abase + row * ROW_B + wcol * 4);
            }
#pragma unroll
            for (int pr = 0; pr < 4; pr++) {
                unsigned r4[4];
                int row  = wn0 + pr * 16 + ((sel >> 1) << 3) + lr;
                int wcol = c * 8 + ((sel & 1) << 2);
                ldm_x4(r4, Bbase + row * ROW_B + wcol * 4);
                b[pr * 2][0]     = r4[0]; b[pr * 2][1]     = r4[1];
                b[pr * 2 + 1][0] = r4[2]; b[pr * 2 + 1][1] = r4[3];
            }
#pragma unroll
            for (int mt = 0; mt < 2; mt++)
#pragma unroll
                for (int nt = 0; nt < 8; nt++)
                    mma_f16(acc[mt][nt], a[mt], b[nt]);
        }
        __syncthreads();
    }

    auto epi_store = [&](int r, int c, float v) {
        if (EPI == 0) {
            if (c < HH) Ch[(size_t)r * HH + c] = __float2half_rn(v);
            else        Ch2[TIX(r, c - HH)] = __float2half_rn(v);
        } else if (EPI == 1) {
            v += bias[c]; v = v * sigmoid_f(v);
            h16 hv = __float2half_rn(v);
            Ch[(size_t)r * HH + c] = hv;
            Ch2[TIX(r, c)] = hv;
        } else if (EPI == 3) {
            v += bias[c];
            v = (v > 20.f) ? v : log1pf(expf(v));
            Cf[TIX(r, c)] = v;
        } else if (EPI == 4) {
            Cf[(size_t)r * FF + c] = v;
        } else {                                   // EPI 5
            Cf[(size_t)r * 128 + c] = v;
        }
    };

#pragma unroll
    for (int mt = 0; mt < 2; mt++) {
        int r = row0 + wm0 + mt * 16 + gid;
#pragma unroll
        for (int nt = 0; nt < 8; nt++) {
            int c = col0 + wn0 + nt * 8 + tig * 2;
            epi_store(r,     c,     acc[mt][nt][0]);
            epi_store(r,     c + 1, acc[mt][nt][1]);
            epi_store(r + 8, c,     acc[mt][nt][2]);
            epi_store(r + 8, c + 1, acc[mt][nt][3]);
        }
    }
}

// ----- proj split-K reduce + epilogue (Bt/Ct time-major fp32, dt fp16) -----
__global__ __launch_bounds__(256)
void proj_red(const float* __restrict__ pp, float* __restrict__ Bt,
              float* __restrict__ Ct, h16* __restrict__ dth)
{
    int idx = blockIdx.x * 256 + threadIdx.x;    // over MROWS*128
    int r = idx >> 7, c = idx & 127;
    float v = 0.f;
#pragma unroll
    for (int s = 0; s < KSPL; s++)
        v += pp[(size_t)s * MROWS * 128 + idx];
    if (c < NN)            Bt[TIX(r, c)] = v;
    else if (c < 2 * NN)   Ct[TIX(r, c - NN)] = v;
    else if (c < PROJC)    dth[(size_t)r * RR + (c - 2 * NN)] = __float2half_rn(v);
}

// ----- chunked scan pass 1: per-chunk local state + transition factor ------
__global__ __launch_bounds__(256)
void scan1_k(const float* __restrict__ dtt, const h16* __restrict__ ut,
             const float* __restrict__ Bt, const float* __restrict__ A_log,
             float* __restrict__ loc, float* __restrict__ pA)
{
    const int w    = blockIdx.x * 8 + (threadIdx.x >> 5);
    const int hi   = w >> 3;
    const int ch   = w & 7;
    const int lane = threadIdx.x & 31;
    const int b    = lane >> 4;
    const int n    = lane & 15;

    const float A = -expf(A_log[hi * NN + n]);

    const float4* dt4 = (const float4*)(dtt + (size_t)hi * MROWS + b * LL + ch * TC);
    const uint2*  u4  = (const uint2*) (ut  + (size_t)hi * MROWS + b * LL + ch * TC);
    const float4* B4  = (const float4*)(Bt  + (size_t)n  * MROWS + b * LL + ch * TC);

    float s = 0.f, sdt = 0.f;
    float4 dtN = dt4[0], vBN = B4[0];
    uint2  uN  = u4[0];

    for (int tb = 0; tb < TC / 4; tb++) {
        float4 dtC = dtN, vBC = vBN;
        uint2  uC  = uN;
        if (tb + 1 < TC / 4) { dtN = dt4[tb + 1]; vBN = B4[tb + 1]; uN = u4[tb + 1]; }

        float uu[4];
        {
            __half2 lo = *(__half2*)&uC.x, hh = *(__half2*)&uC.y;
            uu[0] = __low2float(lo); uu[1] = __high2float(lo);
            uu[2] = __low2float(hh); uu[3] = __high2float(hh);
        }
        const float dts[4] = {dtC.x, dtC.y, dtC.z, dtC.w};
        const float Bv [4] = {vBC.x, vBC.y, vBC.z, vBC.w};
#pragma unroll
        for (int j = 0; j < 4; j++) {
            float dt = fminf(fmaxf(dts[j], 0.001f), 0.1f);
            sdt += dt;
            s = __expf(dt * A) * s + (dt * uu[j]) * Bv[j];
        }
    }
    const int chain = hi * BB + b;
    loc[LOC(chain, ch, n)] = s;
    pA [LOC(chain, ch, n)] = __expf(A * sdt);
}

// ----- chunk combine: sequential stitch of 8 chunk states per chain --------
__global__ __launch_bounds__(256)
void comb_k(const float* __restrict__ loc, const float* __restrict__ pA,
            float* __restrict__ init)
{
    int idx = blockIdx.x * 256 + threadIdx.x;    // over HH*BB*16
    int chain = idx >> 4, n = idx & 15;
    float pv[NCH], lv[NCH];
#pragma unroll
    for (int c = 0; c < NCH; c++) {
        pv[c] = pA [LOC(chain, c, n)];
        lv[c] = loc[LOC(chain, c, n)];
    }
    float s = 0.f;
#pragma unroll
    for (int c = 0; c < NCH; c++) {
        init[LOC(chain, c, n)] = s;
        s = pv[c] * s + lv[c];
    }
}

// ----- chunked scan pass 2: recompute with true init, emit z ---------------
__global__ __launch_bounds__(256)
void scan2_k(const float* __restrict__ dtt, const h16* __restrict__ ut,
             const float* __restrict__ Bt, const float* __restrict__ Ct,
             const float* __restrict__ A_log, const float* __restrict__ D,
             const h16* __restrict__ rest, const float* __restrict__ init,
             h16* __restrict__ zh)
{
    const int w    = blockIdx.x * 8 + (threadIdx.x >> 5);
    const int hi   = w >> 3;
    const int ch   = w & 7;
    const int lane = threadIdx.x & 31;
    const int b    = lane >> 4;
    const int n    = lane & 15;

    const float A  = -expf(A_log[hi * NN + n]);
    const float Dh = D[hi];

    const float4* dt4 = (const float4*)(dtt  + (size_t)hi * MROWS + b * LL + ch * TC);
    const uint2*  u4  = (const uint2*) (ut   + (size_t)hi * MROWS + b * LL + ch * TC);
    const uint2*  rs4 = (const uint2*) (rest + (size_t)hi * MROWS + b * LL + ch * TC);
    const float4* B4  = (const float4*)(Bt   + (size_t)n  * MROWS + b * LL + ch * TC);
    const float4* C4  = (const float4*)(Ct   + (size_t)n  * MROWS + b * LL + ch * TC);

    float s = init[LOC(hi * BB + b, ch, n)];

    float4 dtN = dt4[0], vBN = B4[0], vCN = C4[0];
    uint2  uN  = u4[0],  rN  = rs4[0];

    for (int tb = 0; tb < TC / 4; tb++) {
        float4 dtC = dtN, vBC = vBN, vCC = vCN;
        uint2  uC  = uN,  rC  = rN;
        if (tb + 1 < TC / 4) {
            dtN = dt4[tb + 1]; vBN = B4[tb + 1]; vCN = C4[tb + 1];
            uN  = u4[tb + 1];  rN  = rs4[tb + 1];
        }

        float uu[4];
        {
            __half2 lo = *(__half2*)&uC.x, hh = *(__half2*)&uC.y;
            uu[0] = __low2float(lo); uu[1] = __high2float(lo);
            uu[2] = __low2float(hh); uu[3] = __high2float(hh);
        }
        const float dts[4] = {dtC.x, dtC.y, dtC.z, dtC.w};
        const float Bv [4] = {vBC.x, vBC.y, vBC.z, vBC.w};
        const float Cv [4] = {vCC.x, vCC.y, vCC.z, vCC.w};

        float p[4];
#pragma unroll
        for (int j = 0; j < 4; j++) {
            float dt = fminf(fmaxf(dts[j], 0.001f), 0.1f);
            s = __expf(dt * A) * s + (dt * uu[j]) * Bv[j];
            p[j] = Cv[j] * s;
        }
#pragma unroll
        for (int m = 1; m < 16; m <<= 1) {
#pragma unroll
            for (int j = 0; j < 4; j++)
                p[j] += __shfl_xor_sync(0xffffffffu, p[j], m);
        }

        if (n < 4) {                 // lane n stores timestep tb*4+n
            float rv;
            {
                __half2 lo = *(__half2*)&rC.x, hh = *(__half2*)&rC.y;
                float r4v[4] = {__low2float(lo), __high2float(lo),
                                __low2float(hh), __high2float(hh)};
                rv = r4v[n];
            }
            int t = ch * TC + tb * 4 + n;
            float yv = p[n] + uu[n] * Dh;
            float zv = yv * (rv * sigmoid_f(rv));
            zh[(size_t)(t * BB + b) * HH + hi] = __float2half_rn(zv);
        }
    }
}

// ---------------- launch ---------------------------------------------------
extern "C" void kernel_launch(void* const* d_in, const int* in_sizes, int n_in,
                              void* d_out, int out_size)
{
    const float* x      = (const float*)d_in[0];
    const float* W_in   = (const float*)d_in[1];
    const float* W_conv = (const float*)d_in[2];
    const float* b_conv = (const float*)d_in[3];
    const float* A_log  = (const float*)d_in[4];
    const float* D      = (const float*)d_in[5];
    const float* W_ssm  = (const float*)d_in[6];
    const float* W_dt   = (const float*)d_in[7];
    const float* b_dt   = (const float*)d_in[8];
    const float* W_out  = (const float*)d_in[9];
    float* out = (float*)d_out;

    void* p;
#define SYM(v, s) cudaGetSymbolAddress(&p, s); auto* v = decltype(&s[0])(p)
    SYM(xh, g_xh);   SYM(Win, g_Win);
    SYM(xs, g_xs);   SYM(Wc, g_Wc);
    SYM(uh, g_uh);   SYM(Ws, g_Ws);
    SYM(dth, g_dth); SYM(Wd, g_Wd);
    SYM(zh, g_zh);   SYM(Wo, g_Wo);
    SYM(dtt, g_dtt); SYM(ut, g_ut); SYM(rest, g_rest);
    SYM(Btp, g_Bt);  SYM(Ctp, g_Ct);
    SYM(locp, g_loc); SYM(pAp, g_pA); SYM(initp, g_init);
    SYM(ppp, g_pp);
#undef SYM

    cudaFuncSetAttribute(tc_gemm<0,0,0>, cudaFuncAttributeMaxDynamicSharedMemorySize, SMEM_TOTAL);
    cudaFuncSetAttribute(tc_gemm<1,1,0>, cudaFuncAttributeMaxDynamicSharedMemorySize, SMEM_TOTAL);
    cudaFuncSetAttribute(tc_gemm<3,0,0>, cudaFuncAttributeMaxDynamicSharedMemorySize, SMEM_TOTAL);
    cudaFuncSetAttribute(tc_gemm<4,0,0>, cudaFuncAttributeMaxDynamicSharedMemorySize, SMEM_TOTAL);
    cudaFuncSetAttribute(tc_gemm<5,0,1>, cudaFuncAttributeMaxDynamicSharedMemorySize, SMEM_TOTAL);

    dim3 blk(256);
    dim3 tblk(32, 8);

    // 1) x -> fp16 AND W_conv transpose (fused)
    cvt1_k<<<8192 + 8192, tblk>>>(x, xh, W_conv, Wc);

    // 2) W_in transpose
    trhalf_k<<<dim3(FF / 32, (2 * HH) / 32), tblk>>>(W_in, Win, FF, 2 * HH, 2 * HH);

    // 3) h = x @ W_in : xs -> fp16 g_xs, res -> h16 time-major g_rest
    tc_gemm<0, 0, 0><<<dim3(2 * HH / BN, MROWS / BM), blk, SMEM_TOTAL>>>(
        xh, FF, Win, FF, nullptr, xs, rest, 2 * HH, FF, nullptr);

    // 4) u = silu(conv(xs) + b_conv) -> fp16 g_uh + time-major g_ut [ncu slot]
    tc_gemm<1, 1, 0><<<dim3(HH / BN, MROWS / BM), blk, SMEM_TOTAL>>>(
        xs, HH, Wc, KK * 1024, nullptr, uh, ut, HH, KK * 1024, b_conv);

    // 5) transpose W_ssm / W_dt / W_out
    tr3_k<<<256 + 128 + 2048, tblk>>>(W_ssm, Ws, W_dt, Wd, W_out, Wo);

    // 6) proj split-K partials: grid (KSPL, 16), Kk = HH/KSPL = 256
    tc_gemm<5, 0, 1><<<dim3(KSPL, MROWS / BM), blk, SMEM_TOTAL>>>(
        uh, HH, Ws, HH, ppp, nullptr, nullptr, 128, HH / KSPL, nullptr);

    // 7) proj reduce + epilogue (Bt/Ct time-major, dt fp16)
    proj_red<<<MROWS * 128 / 256, blk>>>(ppp, Btp, Ctp, dth);

    // 8) delta = softplus(dt @ W_dt + b_dt) -> fp32 time-major g_dtt
    tc_gemm<3, 0, 0><<<dim3(HH / BN, MROWS / BM), blk, SMEM_TOTAL>>>(
        dth, RR, Wd, RR, dtt, nullptr, nullptr, HH, RR, b_dt);

    // 9) chunked scan pass 1 (local states + transition factors)
    scan1_k<<<HH * NCH / 8, blk>>>(dtt, ut, Btp, A_log, locp, pAp);

    // 10) combine: stitch chunk initial states
    comb_k<<<HH * BB * 16 / 256, blk>>>(locp, pAp, initp);

    // 11) chunked scan pass 2 -> fp16 g_zh
    scan2_k<<<HH * NCH / 8, blk>>>(dtt, ut, Btp, Ctp, A_log, D, rest, initp, zh);

    // 12) out = z @ W_out -> fp32 out
    tc_gemm<4, 0, 0><<<dim3(FF / BN, MROWS / BM), blk, SMEM_TOTAL>>>(
        zh, HH, Wo, HH, out, nullptr, nullptr, FF, HH, nullptr);
}

// round 17
// speedup vs baseline: 2.9836x; 1.2304x over previous
#include <cuda_runtime.h>
#include <cuda_fp16.h>
#include <cstdint>
#include <math.h>

// Problem constants
#define LL 1024
#define BB 2
#define FF 1024
#define HH 2048
#define NN 16
#define RR 64
#define KK 4
#define MROWS (LL*BB)        // 2048
#define PROJC (RR + 2*NN)    // 96
#define TC 128               // scan chunk length
#define NCH 8                // scan chunks
#define KSPL 8               // proj split-K ways

typedef __half h16;

// ---------------- scratch (device globals: allocation-free) ----------------
__device__ h16 g_xh [(size_t)MROWS * FF];
__device__ h16 g_Win[(size_t)(2*HH) * FF];      // [4096][1024] K-major
__device__ h16 g_xs [(size_t)MROWS * HH];
__device__ h16 g_Wc [(size_t)HH * (KK*1024)];   // [2048][4096]
__device__ h16 g_uh [(size_t)MROWS * HH];       // u row-major (proj GEMM A)
__device__ h16 g_Ws [(size_t)128 * HH];         // [128 pad][2048]
__device__ h16 g_dth[(size_t)MROWS * RR];
__device__ h16 g_Wd [(size_t)HH * RR];          // [2048][64]
__device__ h16 g_zh [(size_t)MROWS * HH];
__device__ h16 g_Wo [(size_t)FF * HH];          // [1024][2048]
// time-major scan inputs
__device__ float g_dtt [(size_t)HH * MROWS];    // delta [hi][b][t]
__device__ h16   g_ut  [(size_t)HH * MROWS];    // u     [hi][b][t]
__device__ h16   g_rest[(size_t)HH * MROWS];    // res   [hi][b][t]
__device__ float g_Bt  [(size_t)BB * LL * NN];  // B     [b][t][n]  (n dense!)
__device__ float g_Ct  [(size_t)BB * LL * NN];  // C     [b][t][n]
// chunked-scan intermediates: chain = hi*BB+b; [chain][ch][n]
__device__ float g_loc [(size_t)HH * BB * NCH * 16];
__device__ float g_pA  [(size_t)HH * BB * NCH * 16];
__device__ float g_init[(size_t)HH * BB * NCH * 16];
// proj split-K partials [split][r][128]
__device__ float g_pp  [(size_t)KSPL * MROWS * 128];

// time-major index for [hi][b][t] tensors: r = t*2+b
#define TIX(r, c) ((size_t)(c) * MROWS + ((r) & 1) * LL + ((r) >> 1))
// index for [b][t][n] tensors: r = t*2+b, c = n
#define BIX(r, c) ((((size_t)((r) & 1) * LL + ((r) >> 1)) << 4) + (c))
#define LOC(chain, ch, n) (((size_t)(chain) * NCH + (ch)) * 16 + (n))

// ---------------- tiling ----------------------------------------------------
#define BM 128
#define BN 128
#define BK 64
#define ROW_B   144                       // 64 halves (128B) + 16B pad
#define ARR_B   (128 * ROW_B)             // 18432 B per operand tile
#define STAGE_B (2 * ARR_B)               // A + B = 36864 B
#define NSTAGE  3
#define SMEM_TOTAL (NSTAGE * STAGE_B)     // 110592 B

__device__ __forceinline__ float sigmoid_f(float x) {
    return 1.f / (1.f + __expf(-x));
}
__device__ __forceinline__ void mma_f16(float* d, const unsigned* a, const unsigned* b) {
    asm volatile(
        "mma.sync.aligned.m16n8k16.row.col.f32.f16.f16.f32 "
        "{%0,%1,%2,%3}, {%4,%5,%6,%7}, {%8,%9}, {%0,%1,%2,%3};\n"
        : "+f"(d[0]), "+f"(d[1]), "+f"(d[2]), "+f"(d[3])
        : "r"(a[0]), "r"(a[1]), "r"(a[2]), "r"(a[3]), "r"(b[0]), "r"(b[1]));
}
__device__ __forceinline__ void ldm_x4(unsigned* r, unsigned saddr) {
    asm volatile("ldmatrix.sync.aligned.m8n8.x4.shared.b16 {%0,%1,%2,%3}, [%4];"
        : "=r"(r[0]), "=r"(r[1]), "=r"(r[2]), "=r"(r[3]) : "r"(saddr));
}
__device__ __forceinline__ void cp16(void* smem_dst, const void* gsrc, bool valid) {
    unsigned s = (unsigned)__cvta_generic_to_shared(smem_dst);
    int sz = valid ? 16 : 0;
    asm volatile("cp.async.cg.shared.global [%0], [%1], 16, %2;\n"
                 :: "r"(s), "l"(gsrc), "r"(sz));
}
#define CP_COMMIT() asm volatile("cp.async.commit_group;\n")
#define CP_WAIT(n)  asm volatile("cp.async.wait_group %0;\n" :: "n"(n))

// ---------------- pre-passes -------------------------------------------------
__device__ __forceinline__ void tr_body(const float* __restrict__ in,
                                        h16* __restrict__ o,
                                        int Kd, int Nd, int Npad,
                                        int k0, int n0)
{
    __shared__ float tile[32][33];
    for (int i = threadIdx.y; i < 32; i += 8) {
        int k = k0 + i, n = n0 + threadIdx.x;
        tile[i][threadIdx.x] = (k < Kd && n < Nd) ? in[(size_t)k * Nd + n] : 0.f;
    }
    __syncthreads();
    for (int i = threadIdx.y; i < 32; i += 8) {
        int n = n0 + i, k = k0 + threadIdx.x;
        if (n < Npad && k < Kd)
            o[(size_t)n * Kd + k] = __float2half_rn(tile[threadIdx.x][i]);
    }
}

__global__ void cvt1_k(const float* __restrict__ x, h16* __restrict__ xh,
                       const float* __restrict__ Wc_in, h16* __restrict__ Wc_o)
{
    int bid = blockIdx.x;
    int t = threadIdx.y * 32 + threadIdx.x;
    if (bid < 8192) {
        int i = bid * 256 + t;
        if (i < MROWS * FF) xh[i] = __float2half_rn(x[i]);
    } else {
        int b2 = bid - 8192;
        int kb = b2 & 127, nb = b2 >> 7;
        tr_body(Wc_in, Wc_o, KK * 1024, HH, HH, kb * 32, nb * 32);
    }
}

__global__ void trhalf_k(const float* __restrict__ in, h16* __restrict__ o,
                         int Kd, int Nd, int Npad)
{
    tr_body(in, o, Kd, Nd, Npad, blockIdx.x * 32, blockIdx.y * 32);
}

__global__ void tr3_k(const float* __restrict__ Ws_in, h16* __restrict__ Ws_o,
                      const float* __restrict__ Wd_in, h16* __restrict__ Wd_o,
                      const float* __restrict__ Wo_in, h16* __restrict__ Wo_o)
{
    int bid = blockIdx.x;
    if (bid < 256) {            // W_ssm
        int kb = bid & 63, nb = bid >> 6;
        tr_body(Ws_in, Ws_o, HH, PROJC, 128, kb * 32, nb * 32);
    } else if (bid < 384) {     // W_dt
        int b2 = bid - 256;
        int kb = b2 & 1, nb = b2 >> 1;
        tr_body(Wd_in, Wd_o, RR, HH, HH, kb * 32, nb * 32);
    } else {                    // W_out
        int b2 = bid - 384;
        int kb = b2 & 63, nb = b2 >> 6;
        tr_body(Wo_in, Wo_o, HH, FF, FF, kb * 32, nb * 32);
    }
}

// ===== fp16 tensor GEMM: 128x128x64 tile, 256 thr (8 warps, 32x64/warp) ====
// EPI 0: GEMM1 (c<HH -> fp16 Ch=xs; else h16 Ch2 = res TIME-MAJOR)
// EPI 1: conv  (silu(v+bias) -> fp16 Ch=u row-major AND Ch2=u time-major)
// EPI 3: delta (softplus(v+bias) -> Cf = dtt TIME-MAJOR fp32)
// EPI 4: out   (Cf plain row-major fp32)
// EPI 5: split-K partial (Cf[r*128+c], SPLITK=1)
template<int EPI, int CONV, int SPLITK>
__global__ __launch_bounds__(256, 2)
void tc_gemm(const h16* __restrict__ A, int lda,
             const h16* __restrict__ B, int ldb,
             float* __restrict__ Cf, h16* __restrict__ Ch, h16* __restrict__ Ch2,
             int Nn, int Kk, const float* __restrict__ bias)
{
    extern __shared__ __align__(16) char smem[];
    const unsigned smb = (unsigned)__cvta_generic_to_shared(smem);

    if (SPLITK) {
        int kb = blockIdx.x * Kk;
        A += kb; B += kb;
        Cf += (size_t)blockIdx.x * MROWS * 128;
    }

    const int tid  = threadIdx.x;
    const int col0 = SPLITK ? 0 : blockIdx.x * BN;
    const int row0 = blockIdx.y * BM;
    const int grp  = CONV ? (col0 >> 10) : 0;
    const int warp = tid >> 5;
    const int lane = tid & 31;
    const int gid  = lane >> 2;
    const int tig  = lane & 3;
    const int wm0  = (warp & 3) * 32;
    const int wn0  = (warp >> 2) * 64;
    const int sel  = lane >> 3;
    const int lr   = lane & 7;

    auto ld_tile = [&](int kt, int stage) {
        char* base = smem + stage * STAGE_B;
#pragma unroll
        for (int i = 0; i < 4; i++) {
            int q = tid + i * 256;
            int m = q >> 3, j = (q & 7) * 8;
            char* dst = base + m * ROW_B + j * 2;
            const h16* src;
            bool valid = true;
            if (CONV) {
                int tap = kt >> 10, ci0 = kt & 1023, shift = 2 * (3 - tap);
                int rs = row0 + m - shift;
                valid = rs >= 0;
                src = A + (size_t)(valid ? rs : 0) * lda + grp * 1024 + ci0 + j;
            } else {
                src = A + (size_t)(row0 + m) * lda + kt + j;
            }
            cp16(dst, src, valid);
        }
#pragma unroll
        for (int i = 0; i < 4; i++) {
            int q = tid + i * 256;
            int n = q >> 3, j = (q & 7) * 8;
            cp16(base + ARR_B + n * ROW_B + j * 2,
                 B + (size_t)(col0 + n) * ldb + kt + j, true);
        }
        CP_COMMIT();
    };

    float acc[2][8][4];
#pragma unroll
    for (int mt = 0; mt < 2; mt++)
#pragma unroll
        for (int nt = 0; nt < 8; nt++)
#pragma unroll
            for (int q = 0; q < 4; q++) acc[mt][nt][q] = 0.f;

    const int T = Kk / BK;
    ld_tile(0, 0);
    if (T > 1) ld_tile(BK, 1);

    for (int t = 0; t < T; t++) {
        const int stage = t % NSTAGE;
        if (t + 1 < T) CP_WAIT(1); else CP_WAIT(0);
        __syncthreads();
        if (t + 2 < T) ld_tile((t + 2) * BK, (t + 2) % NSTAGE);

        const unsigned Abase = smb + stage * STAGE_B;
        const unsigned Bbase = Abase + ARR_B;

#pragma unroll
        for (int c = 0; c < 4; c++) {
            unsigned a[2][4], b[8][2];
#pragma unroll
            for (int mt = 0; mt < 2; mt++) {
                int row  = wm0 + mt * 16 + ((sel & 1) << 3) + lr;
                int wcol = c * 8 + ((sel >> 1) << 2);
                ldm_x4(a[mt], Abase + row * ROW_B + wcol * 4);
            }
#pragma unroll
            for (int pr = 0; pr < 4; pr++) {
                unsigned r4[4];
                int row  = wn0 + pr * 16 + ((sel >> 1) << 3) + lr;
                int wcol = c * 8 + ((sel & 1) << 2);
                ldm_x4(r4, Bbase + row * ROW_B + wcol * 4);
                b[pr * 2][0]     = r4[0]; b[pr * 2][1]     = r4[1];
                b[pr * 2 + 1][0] = r4[2]; b[pr * 2 + 1][1] = r4[3];
            }
#pragma unroll
            for (int mt = 0; mt < 2; mt++)
#pragma unroll
                for (int nt = 0; nt < 8; nt++)
                    mma_f16(acc[mt][nt], a[mt], b[nt]);
        }
        __syncthreads();
    }

    auto epi_store = [&](int r, int c, float v) {
        if (EPI == 0) {
            if (c < HH) Ch[(size_t)r * HH + c] = __float2half_rn(v);
            else        Ch2[TIX(r, c - HH)] = __float2half_rn(v);
        } else if (EPI == 1) {
            v += bias[c]; v = v * sigmoid_f(v);
            h16 hv = __float2half_rn(v);
            Ch[(size_t)r * HH + c] = hv;
            Ch2[TIX(r, c)] = hv;
        } else if (EPI == 3) {
            v += bias[c];
            v = (v > 20.f) ? v : log1pf(expf(v));
            Cf[TIX(r, c)] = v;
        } else if (EPI == 4) {
            Cf[(size_t)r * FF + c] = v;
        } else {                                   // EPI 5
            Cf[(size_t)r * 128 + c] = v;
        }
    };

#pragma unroll
    for (int mt = 0; mt < 2; mt++) {
        int r = row0 + wm0 + mt * 16 + gid;
#pragma unroll
        for (int nt = 0; nt < 8; nt++) {
            int c = col0 + wn0 + nt * 8 + tig * 2;
            epi_store(r,     c,     acc[mt][nt][0]);
            epi_store(r,     c + 1, acc[mt][nt][1]);
            epi_store(r + 8, c,     acc[mt][nt][2]);
            epi_store(r + 8, c + 1, acc[mt][nt][3]);
        }
    }
}

// ----- proj split-K reduce + epilogue (Bt/Ct [b][t][n] fp32, dt fp16) ------
__global__ __launch_bounds__(256)
void proj_red(const float* __restrict__ pp, float* __restrict__ Bt,
              float* __restrict__ Ct, h16* __restrict__ dth)
{
    int idx = blockIdx.x * 256 + threadIdx.x;    // over MROWS*128
    int r = idx >> 7, c = idx & 127;
    float v = 0.f;
#pragma unroll
    for (int s = 0; s < KSPL; s++)
        v += pp[(size_t)s * MROWS * 128 + idx];
    if (c < NN)            Bt[BIX(r, c)] = v;
    else if (c < 2 * NN)   Ct[BIX(r, c - NN)] = v;
    else if (c < PROJC)    dth[(size_t)r * RR + (c - 2 * NN)] = __float2half_rn(v);
}

// ----- chunked scan pass 1: per-chunk local state + transition factor ------
// Bt is [b][t][n]: lane n reads Bt[(b*LL + t)*16 + n] — warp-dense.
__global__ __launch_bounds__(256)
void scan1_k(const float* __restrict__ dtt, const h16* __restrict__ ut,
             const float* __restrict__ Bt, const float* __restrict__ A_log,
             float* __restrict__ loc, float* __restrict__ pA)
{
    const int w    = blockIdx.x * 8 + (threadIdx.x >> 5);
    const int hi   = w >> 3;
    const int ch   = w & 7;
    const int lane = threadIdx.x & 31;
    const int b    = lane >> 4;
    const int n    = lane & 15;

    const float A = -expf(A_log[hi * NN + n]);

    const float4* dt4 = (const float4*)(dtt + (size_t)hi * MROWS + b * LL + ch * TC);
    const uint2*  u4  = (const uint2*) (ut  + (size_t)hi * MROWS + b * LL + ch * TC);
    const float*  Bp  = Bt + (((size_t)b * LL + ch * TC) << 4) + n;

    float s = 0.f, sdt = 0.f;
    float4 dtN = dt4[0];
    uint2  uN  = u4[0];
    float  BvN[4];
#pragma unroll
    for (int j = 0; j < 4; j++) BvN[j] = Bp[j << 4];

    for (int tb = 0; tb < TC / 4; tb++) {
        float4 dtC = dtN;
        uint2  uC  = uN;
        float  Bv[4];
#pragma unroll
        for (int j = 0; j < 4; j++) Bv[j] = BvN[j];
        if (tb + 1 < TC / 4) {
            dtN = dt4[tb + 1]; uN = u4[tb + 1];
            const float* Bn4 = Bp + ((size_t)(tb + 1) << 6);
#pragma unroll
            for (int j = 0; j < 4; j++) BvN[j] = Bn4[j << 4];
        }

        float uu[4];
        {
            __half2 lo = *(__half2*)&uC.x, hh = *(__half2*)&uC.y;
            uu[0] = __low2float(lo); uu[1] = __high2float(lo);
            uu[2] = __low2float(hh); uu[3] = __high2float(hh);
        }
        const float dts[4] = {dtC.x, dtC.y, dtC.z, dtC.w};
#pragma unroll
        for (int j = 0; j < 4; j++) {
            float dt = fminf(fmaxf(dts[j], 0.001f), 0.1f);
            sdt += dt;
            s = __expf(dt * A) * s + (dt * uu[j]) * Bv[j];
        }
    }
    const int chain = hi * BB + b;
    loc[LOC(chain, ch, n)] = s;
    pA [LOC(chain, ch, n)] = __expf(A * sdt);
}

// ----- chunk combine: sequential stitch of 8 chunk states per chain --------
__global__ __launch_bounds__(256)
void comb_k(const float* __restrict__ loc, const float* __restrict__ pA,
            float* __restrict__ init)
{
    int idx = blockIdx.x * 256 + threadIdx.x;    // over HH*BB*16
    int chain = idx >> 4, n = idx & 15;
    float pv[NCH], lv[NCH];
#pragma unroll
    for (int c = 0; c < NCH; c++) {
        pv[c] = pA [LOC(chain, c, n)];
        lv[c] = loc[LOC(chain, c, n)];
    }
    float s = 0.f;
#pragma unroll
    for (int c = 0; c < NCH; c++) {
        init[LOC(chain, c, n)] = s;
        s = pv[c] * s + lv[c];
    }
}

// ----- chunked scan pass 2: recompute with true init, emit z ---------------
__global__ __launch_bounds__(256)
void scan2_k(const float* __restrict__ dtt, const h16* __restrict__ ut,
             const float* __restrict__ Bt, const float* __restrict__ Ct,
             const float* __restrict__ A_log, const float* __restrict__ D,
             const h16* __restrict__ rest, const float* __restrict__ init,
             h16* __restrict__ zh)
{
    const int w    = blockIdx.x * 8 + (threadIdx.x >> 5);
    const int hi   = w >> 3;
    const int ch   = w & 7;
    const int lane = threadIdx.x & 31;
    const int b    = lane >> 4;
    const int n    = lane & 15;

    const float A  = -expf(A_log[hi * NN + n]);
    const float Dh = D[hi];

    const float4* dt4 = (const float4*)(dtt  + (size_t)hi * MROWS + b * LL + ch * TC);
    const uint2*  u4  = (const uint2*) (ut   + (size_t)hi * MROWS + b * LL + ch * TC);
    const uint2*  rs4 = (const uint2*) (rest + (size_t)hi * MROWS + b * LL + ch * TC);
    const float*  Bp  = Bt + (((size_t)b * LL + ch * TC) << 4) + n;
    const float*  Cp  = Ct + (((size_t)b * LL + ch * TC) << 4) + n;

    float s = init[LOC(hi * BB + b, ch, n)];

    float4 dtN = dt4[0];
    uint2  uN  = u4[0], rN = rs4[0];
    float  BvN[4], CvN[4];
#pragma unroll
    for (int j = 0; j < 4; j++) { BvN[j] = Bp[j << 4]; CvN[j] = Cp[j << 4]; }

    for (int tb = 0; tb < TC / 4; tb++) {
        float4 dtC = dtN;
        uint2  uC  = uN, rC = rN;
        float  Bv[4], Cv[4];
#pragma unroll
        for (int j = 0; j < 4; j++) { Bv[j] = BvN[j]; Cv[j] = CvN[j]; }
        if (tb + 1 < TC / 4) {
            dtN = dt4[tb + 1]; uN = u4[tb + 1]; rN = rs4[tb + 1];
            const float* Bn4 = Bp + ((size_t)(tb + 1) << 6);
            const float* Cn4 = Cp + ((size_t)(tb + 1) << 6);
#pragma unroll
            for (int j = 0; j < 4; j++) { BvN[j] = Bn4[j << 4]; CvN[j] = Cn4[j << 4]; }
        }

        float uu[4];
        {
            __half2 lo = *(__half2*)&uC.x, hh = *(__half2*)&uC.y;
            uu[0] = __low2float(lo); uu[1] = __high2float(lo);
            uu[2] = __low2float(hh); uu[3] = __high2float(hh);
        }
        const float dts[4] = {dtC.x, dtC.y, dtC.z, dtC.w};

        float p[4];
#pragma unroll
        for (int j = 0; j < 4; j++) {
            float dt = fminf(fmaxf(dts[j], 0.001f), 0.1f);
            s = __expf(dt * A) * s + (dt * uu[j]) * Bv[j];
            p[j] = Cv[j] * s;
        }
#pragma unroll
        for (int m = 1; m < 16; m <<= 1) {
#pragma unroll
            for (int j = 0; j < 4; j++)
                p[j] += __shfl_xor_sync(0xffffffffu, p[j], m);
        }

        if (n < 4) {                 // lane n stores timestep tb*4+n
            float rv;
            {
                __half2 lo = *(__half2*)&rC.x, hh = *(__half2*)&rC.y;
                float r4v[4] = {__low2float(lo), __high2float(lo),
                                __low2float(hh), __high2float(hh)};
                rv = r4v[n];
            }
            int t = ch * TC + tb * 4 + n;
            float yv = p[n] + uu[n] * Dh;
            float zv = yv * (rv * sigmoid_f(rv));
            zh[(size_t)(t * BB + b) * HH + hi] = __float2half_rn(zv);
        }
    }
}

// ---------------- launch ---------------------------------------------------
extern "C" void kernel_launch(void* const* d_in, const int* in_sizes, int n_in,
                              void* d_out, int out_size)
{
    const float* x      = (const float*)d_in[0];
    const float* W_in   = (const float*)d_in[1];
    const float* W_conv = (const float*)d_in[2];
    const float* b_conv = (const float*)d_in[3];
    const float* A_log  = (const float*)d_in[4];
    const float* D      = (const float*)d_in[5];
    const float* W_ssm  = (const float*)d_in[6];
    const float* W_dt   = (const float*)d_in[7];
    const float* b_dt   = (const float*)d_in[8];
    const float* W_out  = (const float*)d_in[9];
    float* out = (float*)d_out;

    void* p;
#define SYM(v, s) cudaGetSymbolAddress(&p, s); auto* v = decltype(&s[0])(p)
    SYM(xh, g_xh);   SYM(Win, g_Win);
    SYM(xs, g_xs);   SYM(Wc, g_Wc);
    SYM(uh, g_uh);   SYM(Ws, g_Ws);
    SYM(dth, g_dth); SYM(Wd, g_Wd);
    SYM(zh, g_zh);   SYM(Wo, g_Wo);
    SYM(dtt, g_dtt); SYM(ut, g_ut); SYM(rest, g_rest);
    SYM(Btp, g_Bt);  SYM(Ctp, g_Ct);
    SYM(locp, g_loc); SYM(pAp, g_pA); SYM(initp, g_init);
    SYM(ppp, g_pp);
#undef SYM

    cudaFuncSetAttribute(tc_gemm<0,0,0>, cudaFuncAttributeMaxDynamicSharedMemorySize, SMEM_TOTAL);
    cudaFuncSetAttribute(tc_gemm<1,1,0>, cudaFuncAttributeMaxDynamicSharedMemorySize, SMEM_TOTAL);
    cudaFuncSetAttribute(tc_gemm<3,0,0>, cudaFuncAttributeMaxDynamicSharedMemorySize, SMEM_TOTAL);
    cudaFuncSetAttribute(tc_gemm<4,0,0>, cudaFuncAttributeMaxDynamicSharedMemorySize, SMEM_TOTAL);
    cudaFuncSetAttribute(tc_gemm<5,0,1>, cudaFuncAttributeMaxDynamicSharedMemorySize, SMEM_TOTAL);

    dim3 blk(256);
    dim3 tblk(32, 8);

    // 1) x -> fp16 AND W_conv transpose (fused)
    cvt1_k<<<8192 + 8192, tblk>>>(x, xh, W_conv, Wc);

    // 2) W_in transpose
    trhalf_k<<<dim3(FF / 32, (2 * HH) / 32), tblk>>>(W_in, Win, FF, 2 * HH, 2 * HH);

    // 3) h = x @ W_in : xs -> fp16 g_xs, res -> h16 time-major g_rest
    tc_gemm<0, 0, 0><<<dim3(2 * HH / BN, MROWS / BM), blk, SMEM_TOTAL>>>(
        xh, FF, Win, FF, nullptr, xs, rest, 2 * HH, FF, nullptr);

    // 4) u = silu(conv(xs) + b_conv) -> fp16 g_uh + time-major g_ut [ncu slot]
    tc_gemm<1, 1, 0><<<dim3(HH / BN, MROWS / BM), blk, SMEM_TOTAL>>>(
        xs, HH, Wc, KK * 1024, nullptr, uh, ut, HH, KK * 1024, b_conv);

    // 5) transpose W_ssm / W_dt / W_out
    tr3_k<<<256 + 128 + 2048, tblk>>>(W_ssm, Ws, W_dt, Wd, W_out, Wo);

    // 6) proj split-K partials: grid (KSPL, 16), Kk = HH/KSPL = 256
    tc_gemm<5, 0, 1><<<dim3(KSPL, MROWS / BM), blk, SMEM_TOTAL>>>(
        uh, HH, Ws, HH, ppp, nullptr, nullptr, 128, HH / KSPL, nullptr);

    // 7) proj reduce + epilogue (Bt/Ct [b][t][n], dt fp16)
    proj_red<<<MROWS * 128 / 256, blk>>>(ppp, Btp, Ctp, dth);

    // 8) delta = softplus(dt @ W_dt + b_dt) -> fp32 time-major g_dtt
    tc_gemm<3, 0, 0><<<dim3(HH / BN, MROWS / BM), blk, SMEM_TOTAL>>>(
        dth, RR, Wd, RR, dtt, nullptr, nullptr, HH, RR, b_dt);

    // 9) chunked scan pass 1 (local states + transition factors)
    scan1_k<<<HH * NCH / 8, blk>>>(dtt, ut, Btp, A_log, locp, pAp);

    // 10) combine: stitch chunk initial states
    comb_k<<<HH * BB * 16 / 256, blk>>>(locp, pAp, initp);

    // 11) chunked scan pass 2 -> fp16 g_zh
    scan2_k<<<HH * NCH / 8, blk>>>(dtt, ut, Btp, Ctp, A_log, D, rest, initp, zh);

    // 12) out = z @ W_out -> fp32 out
    tc_gemm<4, 0, 0><<<dim3(FF / BN, MROWS / BM), blk, SMEM_TOTAL>>>(
        zh, HH, Wo, HH, out, nullptr, nullptr, FF, HH, nullptr);
}